// round 2
// baseline (speedup 1.0000x reference)
#include <cuda_runtime.h>
#include <cuda_bf16.h>

// Problem constants
#define NN 50000
#define NE 800000
#define DD 128

// ---------------- device scratch (static, no allocation) ----------------
__device__ int   g_cnt[NN];
__device__ int   g_rowptr[NN + 1];
__device__ int   g_woff[NN];
__device__ int   g_ecol[NE];
__device__ float g_eval[NE];
__device__ float g_support[(size_t)NN * 128];
__device__ float g_g1[(size_t)NN * 128];
__device__ float g_g2[(size_t)NN * 128];
__device__ float g_g3[(size_t)NN * 128];
__device__ float g_h1[(size_t)NN * 128];
__device__ float g_h2[(size_t)NN * 64];

// ---------------- CSR build ----------------
__global__ void zero_cnt_kernel(int* __restrict__ cnt, int n) {
    int i = blockIdx.x * blockDim.x + threadIdx.x;
    if (i < n) cnt[i] = 0;
}

__global__ void hist_kernel(const int* __restrict__ row, int* __restrict__ cnt, int e) {
    int i = blockIdx.x * blockDim.x + threadIdx.x;
    if (i < e) atomicAdd(&cnt[row[i]], 1);
}

// single-block (1024 threads) exclusive scan over cnt -> rowptr, woff
__global__ void scan_kernel(const int* __restrict__ cnt, int* __restrict__ rowptr,
                            int* __restrict__ woff, int n) {
    __shared__ int warp_sums[32];
    __shared__ int s_carry;
    int tid = threadIdx.x, lane = tid & 31, wid = tid >> 5;
    if (tid == 0) s_carry = 0;
    __syncthreads();
    for (int base = 0; base < n; base += 1024) {
        int carry = s_carry;
        int idx = base + tid;
        int x = (idx < n) ? cnt[idx] : 0;
        int v = x;
        #pragma unroll
        for (int off = 1; off < 32; off <<= 1) {
            int y = __shfl_up_sync(0xffffffffu, v, off);
            if (lane >= off) v += y;
        }
        if (lane == 31) warp_sums[wid] = v;
        __syncthreads();
        if (wid == 0) {
            int w = warp_sums[lane];
            #pragma unroll
            for (int off = 1; off < 32; off <<= 1) {
                int y = __shfl_up_sync(0xffffffffu, w, off);
                if (lane >= off) w += y;
            }
            warp_sums[lane] = w;
        }
        __syncthreads();
        int woffs = (wid > 0) ? warp_sums[wid - 1] : 0;
        int incl = v + woffs;
        if (idx < n) {
            int e = carry + incl - x;
            rowptr[idx] = e;
            woff[idx] = e;
        }
        __syncthreads();
        if (tid == 1023) s_carry = carry + incl;
        __syncthreads();
    }
    if (threadIdx.x == 0) rowptr[n] = s_carry;
}

__global__ void scatter_kernel(const int* __restrict__ row, const int* __restrict__ col,
                               const float* __restrict__ vals, int* __restrict__ woff,
                               int* __restrict__ ecol, float* __restrict__ eval, int e) {
    int i = blockIdx.x * blockDim.x + threadIdx.x;
    if (i < e) {
        int r = row[i];
        int p = atomicAdd(&woff[r], 1);
        ecol[p] = col[i];
        eval[p] = vals[i];
    }
}

// ---------------- dense GEMM: out[M x BN] = X[M x 128*NSRC] @ W[128*NSRC x BN] ----------------
// BM=128, BK=32, 256 threads, thread tile 8 x (BN/16)
template <int BN, int NSRC, bool RELU>
__global__ __launch_bounds__(256) void gemm_kernel(
    const float* __restrict__ x0, const float* __restrict__ x1, const float* __restrict__ x2,
    const float* __restrict__ W, const float* __restrict__ bias,
    float* __restrict__ out, int M)
{
    constexpr int TN = BN / 16;  // 8 or 4
    __shared__ float XsT[32][132];     // transposed X tile (pad 4 to cut STS conflicts, keep 16B align)
    __shared__ float Ws[32][BN];

    const int tid = threadIdx.x;
    const int tx = tid & 15;
    const int ty = tid >> 4;
    const int m0 = blockIdx.x * 128;

    float acc[8][TN];
    #pragma unroll
    for (int r = 0; r < 8; r++)
        #pragma unroll
        for (int c = 0; c < TN; c++) acc[r][c] = 0.f;

    for (int chunk = 0; chunk < NSRC * 4; chunk++) {
        const int kbase = chunk * 32;
        const float* xsrc = x0;
        if (NSRC > 1) {
            if (kbase >= 256) xsrc = x2;
            else if (kbase >= 128) xsrc = x1;
        }
        const int kk = kbase & 127;

        // X tile: 128 rows x 32 cols = 1024 float4, 4 per thread (coalesced), transpose into XsT
        #pragma unroll
        for (int i = 0; i < 4; i++) {
            int f = tid + 256 * i;
            int m = f >> 3;      // row 0..127
            int k4 = f & 7;      // float4 col 0..7
            float4 v = make_float4(0.f, 0.f, 0.f, 0.f);
            int gm = m0 + m;
            if (gm < M) v = *(const float4*)(xsrc + (size_t)gm * 128 + kk + 4 * k4);
            XsT[4 * k4 + 0][m] = v.x;
            XsT[4 * k4 + 1][m] = v.y;
            XsT[4 * k4 + 2][m] = v.z;
            XsT[4 * k4 + 3][m] = v.w;
        }
        // W tile: 32 rows x BN cols
        #pragma unroll
        for (int i = 0; i < BN / 32; i++) {
            int f = tid + 256 * i;
            int k = f / (BN / 4);
            int c4 = f % (BN / 4);
            float4 v = *(const float4*)(W + (size_t)(kbase + k) * BN + 4 * c4);
            *(float4*)&Ws[k][4 * c4] = v;
        }
        __syncthreads();

        #pragma unroll
        for (int k = 0; k < 32; k++) {
            float a[8];
            *(float4*)&a[0] = *(const float4*)&XsT[k][ty * 8];
            *(float4*)&a[4] = *(const float4*)&XsT[k][ty * 8 + 4];
            float b[TN];
            #pragma unroll
            for (int c4 = 0; c4 < TN / 4; c4++)
                *(float4*)&b[4 * c4] = *(const float4*)&Ws[k][tx * TN + 4 * c4];
            #pragma unroll
            for (int r = 0; r < 8; r++)
                #pragma unroll
                for (int c = 0; c < TN; c++)
                    acc[r][c] += a[r] * b[c];
        }
        __syncthreads();
    }

    #pragma unroll
    for (int r = 0; r < 8; r++) {
        int gm = m0 + ty * 8 + r;
        if (gm < M) {
            #pragma unroll
            for (int c4 = 0; c4 < TN / 4; c4++) {
                int col = tx * TN + 4 * c4;
                float4 o;
                o.x = acc[r][4 * c4 + 0];
                o.y = acc[r][4 * c4 + 1];
                o.z = acc[r][4 * c4 + 2];
                o.w = acc[r][4 * c4 + 3];
                if (bias != nullptr) {
                    o.x += __ldg(&bias[col + 0]);
                    o.y += __ldg(&bias[col + 1]);
                    o.z += __ldg(&bias[col + 2]);
                    o.w += __ldg(&bias[col + 3]);
                }
                if (RELU) {
                    o.x = fmaxf(o.x, 0.f); o.y = fmaxf(o.y, 0.f);
                    o.z = fmaxf(o.z, 0.f); o.w = fmaxf(o.w, 0.f);
                }
                *(float4*)(out + (size_t)gm * BN + col) = o;
            }
        }
    }
}

// ---------------- SpMM aggregation: out[n] = relu(sum_e val*support[col] + b) ----------------
// one 128-thread block per node, thread = feature dim
__global__ __launch_bounds__(128) void agg_kernel(
    const float* __restrict__ support, const int* __restrict__ rowptr,
    const int* __restrict__ ecol, const float* __restrict__ eval,
    const float* __restrict__ bias, float* __restrict__ out)
{
    const int node = blockIdx.x;
    const int d = threadIdx.x;
    const int s = __ldg(&rowptr[node]);
    const int e = __ldg(&rowptr[node + 1]);
    float acc = 0.f;
    for (int i = s; i < e; i++) {
        int c = __ldg(&ecol[i]);
        float v = __ldg(&eval[i]);
        acc += v * __ldg(&support[(size_t)c * 128 + d]);
    }
    out[(size_t)node * 128 + d] = fmaxf(acc + __ldg(&bias[d]), 0.f);
}

// ---------------- final tiny layer: logits[n] = h2[n,:64] @ fcW3[64x2] + fcb3 ----------------
__global__ void mlp3_kernel(const float* __restrict__ h2, const float* __restrict__ W,
                            const float* __restrict__ b, float* __restrict__ out, int M)
{
    int n = blockIdx.x * blockDim.x + threadIdx.x;
    if (n >= M) return;
    float s0 = __ldg(&b[0]);
    float s1 = __ldg(&b[1]);
    const float* h = h2 + (size_t)n * 64;
    #pragma unroll
    for (int k4 = 0; k4 < 16; k4++) {
        float4 hv = *(const float4*)(h + 4 * k4);
        float4 w0, w1;
        w0.x = __ldg(&W[(4 * k4 + 0) * 2 + 0]); w1.x = __ldg(&W[(4 * k4 + 0) * 2 + 1]);
        w0.y = __ldg(&W[(4 * k4 + 1) * 2 + 0]); w1.y = __ldg(&W[(4 * k4 + 1) * 2 + 1]);
        w0.z = __ldg(&W[(4 * k4 + 2) * 2 + 0]); w1.z = __ldg(&W[(4 * k4 + 2) * 2 + 1]);
        w0.w = __ldg(&W[(4 * k4 + 3) * 2 + 0]); w1.w = __ldg(&W[(4 * k4 + 3) * 2 + 1]);
        s0 += hv.x * w0.x + hv.y * w0.y + hv.z * w0.z + hv.w * w0.w;
        s1 += hv.x * w1.x + hv.y * w1.y + hv.z * w1.z + hv.w * w1.w;
    }
    out[2 * n + 0] = s0;
    out[2 * n + 1] = s1;
}

// ---------------- launch ----------------
static void* sym_addr(const void* symbol) {
    void* p = nullptr;
    cudaGetSymbolAddress(&p, symbol);
    return p;
}

extern "C" void kernel_launch(void* const* d_in, const int* in_sizes, int n_in,
                              void* d_out, int out_size) {
    const int*   adj_row = (const int*)d_in[0];
    const int*   adj_col = (const int*)d_in[1];
    const float* adj_val = (const float*)d_in[2];
    const float* xin     = (const float*)d_in[3];
    // d_in[4] = graph_indicator (unused by reference)
    const float* W1 = (const float*)d_in[5];
    const float* b1 = (const float*)d_in[6];
    const float* W2 = (const float*)d_in[7];
    const float* b2 = (const float*)d_in[8];
    const float* W3 = (const float*)d_in[9];
    const float* b3 = (const float*)d_in[10];
    const float* fcW1 = (const float*)d_in[11];
    const float* fcb1 = (const float*)d_in[12];
    const float* fcW2 = (const float*)d_in[13];
    const float* fcb2 = (const float*)d_in[14];
    const float* fcW3 = (const float*)d_in[15];
    const float* fcb3 = (const float*)d_in[16];

    const int E = in_sizes[0];
    const int M = in_sizes[4];

    int*   cnt     = (int*)sym_addr(g_cnt);
    int*   rowptr  = (int*)sym_addr(g_rowptr);
    int*   woff    = (int*)sym_addr(g_woff);
    int*   ecol    = (int*)sym_addr(g_ecol);
    float* eval    = (float*)sym_addr(g_eval);
    float* support = (float*)sym_addr(g_support);
    float* gg1     = (float*)sym_addr(g_g1);
    float* gg2     = (float*)sym_addr(g_g2);
    float* gg3     = (float*)sym_addr(g_g3);
    float* h1      = (float*)sym_addr(g_h1);
    float* h2      = (float*)sym_addr(g_h2);
    float* out     = (float*)d_out;

    const int gemm_blocks = (M + 127) / 128;

    // CSR build
    zero_cnt_kernel<<<(M + 255) / 256, 256>>>(cnt, M);
    hist_kernel<<<(E + 255) / 256, 256>>>(adj_row, cnt, E);
    scan_kernel<<<1, 1024>>>(cnt, rowptr, woff, M);
    scatter_kernel<<<(E + 255) / 256, 256>>>(adj_row, adj_col, adj_val, woff, ecol, eval, E);

    // GCN layer 1
    gemm_kernel<128, 1, false><<<gemm_blocks, 256>>>(xin, nullptr, nullptr, W1, nullptr, support, M);
    agg_kernel<<<M, 128>>>(support, rowptr, ecol, eval, b1, gg1);
    // GCN layer 2
    gemm_kernel<128, 1, false><<<gemm_blocks, 256>>>(gg1, nullptr, nullptr, W2, nullptr, support, M);
    agg_kernel<<<M, 128>>>(support, rowptr, ecol, eval, b2, gg2);
    // GCN layer 3
    gemm_kernel<128, 1, false><<<gemm_blocks, 256>>>(gg2, nullptr, nullptr, W3, nullptr, support, M);
    agg_kernel<<<M, 128>>>(support, rowptr, ecol, eval, b3, gg3);

    // MLP: concat [g1,g2,g3] handled inside the GEMM via 3 source pointers
    gemm_kernel<128, 3, true><<<gemm_blocks, 256>>>(gg1, gg2, gg3, fcW1, fcb1, h1, M);
    gemm_kernel<64, 1, true><<<gemm_blocks, 256>>>(h1, nullptr, nullptr, fcW2, fcb2, h2, M);
    mlp3_kernel<<<(M + 255) / 256, 256>>>(h2, fcW3, fcb3, out, M);
}

// round 9
// speedup vs baseline: 1.3034x; 1.3034x over previous
#include <cuda_runtime.h>
#include <cuda_bf16.h>
#include <cstdint>

// Problem constants
#define NN 50000
#define NE 800000

// ---------------- device scratch (static, no allocation) ----------------
__device__ int   g_cnt[NN];
__device__ int   g_rowptr[NN + 1];
__device__ int   g_woff[NN];
__device__ int   g_ecol[NE];
__device__ float g_eval[NE];
__device__ float g_support[(size_t)NN * 128];
__device__ float g_g1[(size_t)NN * 128];
__device__ float g_g2[(size_t)NN * 128];
__device__ float g_g3[(size_t)NN * 128];
__device__ float g_h1[(size_t)NN * 128];
__device__ float g_h2[(size_t)NN * 64];
__device__ __nv_bfloat16 g_wthi[128 * 384];
__device__ __nv_bfloat16 g_wtlo[128 * 384];

// ---------------- helpers ----------------
__device__ __forceinline__ uint32_t smem_u32(const void* p) {
    uint32_t a;
    asm("{ .reg .u64 t; cvta.to.shared.u64 t, %1; cvt.u32.u64 %0, t; }" : "=r"(a) : "l"(p));
    return a;
}

#define LDSM4(r, addr) \
    asm volatile("ldmatrix.sync.aligned.m8n8.x4.shared.b16 {%0,%1,%2,%3}, [%4];" \
        : "=r"((r)[0]), "=r"((r)[1]), "=r"((r)[2]), "=r"((r)[3]) : "r"(addr))

#define MMA16816(d, a, b0, b1) \
    asm volatile("mma.sync.aligned.m16n8k16.row.col.f32.bf16.bf16.f32 " \
        "{%0,%1,%2,%3}, {%4,%5,%6,%7}, {%8,%9}, {%0,%1,%2,%3};" \
        : "+f"((d)[0]), "+f"((d)[1]), "+f"((d)[2]), "+f"((d)[3]) \
        : "r"((a)[0]), "r"((a)[1]), "r"((a)[2]), "r"((a)[3]), "r"(b0), "r"(b1))

// ---------------- CSR build ----------------
__global__ void zero_cnt_kernel(int* __restrict__ cnt, int n) {
    int i = blockIdx.x * blockDim.x + threadIdx.x;
    if (i < n) cnt[i] = 0;
}

__global__ void hist_kernel(const int* __restrict__ row, int* __restrict__ cnt, int e) {
    int i = blockIdx.x * blockDim.x + threadIdx.x;
    if (i < e) atomicAdd(&cnt[row[i]], 1);
}

__global__ void scan_kernel(const int* __restrict__ cnt, int* __restrict__ rowptr,
                            int* __restrict__ woff, int n) {
    __shared__ int warp_sums[32];
    __shared__ int s_carry;
    int tid = threadIdx.x, lane = tid & 31, wid = tid >> 5;
    if (tid == 0) s_carry = 0;
    __syncthreads();
    for (int base = 0; base < n; base += 1024) {
        int carry = s_carry;
        int idx = base + tid;
        int x = (idx < n) ? cnt[idx] : 0;
        int v = x;
        #pragma unroll
        for (int off = 1; off < 32; off <<= 1) {
            int y = __shfl_up_sync(0xffffffffu, v, off);
            if (lane >= off) v += y;
        }
        if (lane == 31) warp_sums[wid] = v;
        __syncthreads();
        if (wid == 0) {
            int w = warp_sums[lane];
            #pragma unroll
            for (int off = 1; off < 32; off <<= 1) {
                int y = __shfl_up_sync(0xffffffffu, w, off);
                if (lane >= off) w += y;
            }
            warp_sums[lane] = w;
        }
        __syncthreads();
        int woffs = (wid > 0) ? warp_sums[wid - 1] : 0;
        int incl = v + woffs;
        if (idx < n) {
            int e = carry + incl - x;
            rowptr[idx] = e;
            woff[idx] = e;
        }
        __syncthreads();
        if (tid == 1023) s_carry = carry + incl;
        __syncthreads();
    }
    if (threadIdx.x == 0) rowptr[n] = s_carry;
}

__global__ void scatter_kernel(const int* __restrict__ row, const int* __restrict__ col,
                               const float* __restrict__ vals, int* __restrict__ woff,
                               int* __restrict__ ecol, float* __restrict__ eval, int e) {
    int i = blockIdx.x * blockDim.x + threadIdx.x;
    if (i < e) {
        int r = row[i];
        int p = atomicAdd(&woff[r], 1);
        ecol[p] = col[i];
        eval[p] = vals[i];
    }
}

// ---------------- weight transpose + bf16 split: W[K][N] -> WT hi/lo [N][K] ----------------
__global__ void wsplit_kernel(const float* __restrict__ W, __nv_bfloat16* __restrict__ hiT,
                              __nv_bfloat16* __restrict__ loT, int K, int N) {
    int i = blockIdx.x * blockDim.x + threadIdx.x;
    if (i >= K * N) return;
    int k = i / N, n = i % N;
    float v = W[i];
    __nv_bfloat16 h = __float2bfloat16(v);
    float r = v - __bfloat162float(h);
    hiT[n * K + k] = h;
    loT[n * K + k] = __float2bfloat16(r);
}

// ---------------- HMMA GEMM: out[M x BN] = relu?(X[M x 128*NCHUNK] @ WT^T + bias) ----------------
// BM=128, 256 threads (8 warps x 16 rows). bf16 split: D = Ahi*Bhi + Ahi*Blo + Alo*Bhi.
// smem rows padded to 136 bf16 (272 B = 17 x 16B) -> conflict-free ldmatrix.
template <int BN, int NCHUNK, bool RELU>
__global__ __launch_bounds__(256, 1)
void gemm_mma(const float* __restrict__ x0, const float* __restrict__ x1,
              const float* __restrict__ x2,
              const __nv_bfloat16* __restrict__ WThi, const __nv_bfloat16* __restrict__ WTlo,
              const float* __restrict__ bias, float* __restrict__ out, int M)
{
    extern __shared__ char smem[];
    constexpr int LDAB = 272;                 // bytes per smem row
    constexpr int A_BYTES = 128 * LDAB;       // 34816
    constexpr int B_BYTES = BN * LDAB;
    char* pAhi = smem;
    char* pAlo = smem + A_BYTES;
    char* pBhi = smem + 2 * A_BYTES;
    char* pBlo = smem + 2 * A_BYTES + B_BYTES;

    const int tid = threadIdx.x, wid = tid >> 5, lane = tid & 31;
    const int m0 = blockIdx.x * 128;
    const int Ktot = NCHUNK * 128;
    constexpr int NT = BN / 8;

    float acc[NT][4];
    #pragma unroll
    for (int t = 0; t < NT; t++)
        #pragma unroll
        for (int j = 0; j < 4; j++) acc[t][j] = 0.f;

    const uint32_t sb = smem_u32(smem);
    const int mat = lane >> 3, r8 = lane & 7;
    const uint32_t a_hi_base = sb + LDAB * (wid * 16 + (mat & 1) * 8 + r8) + 16 * (mat >> 1);
    const uint32_t a_lo_base = a_hi_base + A_BYTES;
    const uint32_t b_hi_base = sb + 2 * A_BYTES + LDAB * ((mat >> 1) * 8 + r8) + 16 * (mat & 1);
    const uint32_t b_lo_base = b_hi_base + B_BYTES;

    const float* srcs[3] = { x0, x1, x2 };

    for (int c = 0; c < NCHUNK; c++) {
        if (c > 0) __syncthreads();
        const float* xs = srcs[c];
        // stage A: 128 x 128 fp32 -> bf16 hi/lo, row-major padded
        #pragma unroll
        for (int i = 0; i < 16; i++) {
            int f = tid + 256 * i;
            int row = f >> 5;
            int col = (f & 31) * 4;
            float4 v = make_float4(0.f, 0.f, 0.f, 0.f);
            int gm = m0 + row;
            if (gm < M) v = *(const float4*)(xs + (size_t)gm * 128 + col);
            __nv_bfloat162 h01 = __floats2bfloat162_rn(v.x, v.y);
            __nv_bfloat162 h23 = __floats2bfloat162_rn(v.z, v.w);
            __nv_bfloat162 l01 = __floats2bfloat162_rn(v.x - __bfloat162float(h01.x),
                                                       v.y - __bfloat162float(h01.y));
            __nv_bfloat162 l23 = __floats2bfloat162_rn(v.z - __bfloat162float(h23.x),
                                                       v.w - __bfloat162float(h23.y));
            int off = LDAB * row + 2 * col;
            *(__nv_bfloat162*)(pAhi + off)     = h01;
            *(__nv_bfloat162*)(pAhi + off + 4) = h23;
            *(__nv_bfloat162*)(pAlo + off)     = l01;
            *(__nv_bfloat162*)(pAlo + off + 4) = l23;
        }
        // stage B: BN x 128 bf16 hi/lo from WT [N][Ktot]
        #pragma unroll
        for (int i = 0; i < BN / 16; i++) {
            int f = tid + 256 * i;
            int row = f >> 4;
            int col = (f & 15) * 8;
            uint4 vh = *(const uint4*)(WThi + (size_t)row * Ktot + c * 128 + col);
            uint4 vl = *(const uint4*)(WTlo + (size_t)row * Ktot + c * 128 + col);
            int off = LDAB * row + 2 * col;
            *(uint4*)(pBhi + off) = vh;
            *(uint4*)(pBlo + off) = vl;
        }
        __syncthreads();

        #pragma unroll
        for (int ks = 0; ks < 8; ks++) {
            uint32_t ah[4], al[4];
            LDSM4(ah, a_hi_base + 32 * ks);
            LDSM4(al, a_lo_base + 32 * ks);
            #pragma unroll
            for (int np = 0; np < NT / 2; np++) {
                uint32_t bh[4], bl[4];
                LDSM4(bh, b_hi_base + 16 * LDAB * np + 32 * ks);
                LDSM4(bl, b_lo_base + 16 * LDAB * np + 32 * ks);
                MMA16816(acc[2 * np],     ah, bh[0], bh[1]);
                MMA16816(acc[2 * np],     ah, bl[0], bl[1]);
                MMA16816(acc[2 * np],     al, bh[0], bh[1]);
                MMA16816(acc[2 * np + 1], ah, bh[2], bh[3]);
                MMA16816(acc[2 * np + 1], ah, bl[2], bl[3]);
                MMA16816(acc[2 * np + 1], al, bh[2], bh[3]);
            }
        }
    }

    // epilogue: D frag -> rows (wid*16 + lane>>2) and +8, cols 8t + (lane&3)*2
    const int row0 = m0 + wid * 16 + (lane >> 2);
    const int coff = (lane & 3) * 2;
    #pragma unroll
    for (int t = 0; t < NT; t++) {
        int col = 8 * t + coff;
        float b0 = 0.f, b1 = 0.f;
        if (bias != nullptr) { b0 = __ldg(&bias[col]); b1 = __ldg(&bias[col + 1]); }
        float2 v0 = make_float2(acc[t][0] + b0, acc[t][1] + b1);
        float2 v1 = make_float2(acc[t][2] + b0, acc[t][3] + b1);
        if (RELU) {
            v0.x = fmaxf(v0.x, 0.f); v0.y = fmaxf(v0.y, 0.f);
            v1.x = fmaxf(v1.x, 0.f); v1.y = fmaxf(v1.y, 0.f);
        }
        if (row0 < M)     *(float2*)(out + (size_t)row0 * BN + col) = v0;
        if (row0 + 8 < M) *(float2*)(out + (size_t)(row0 + 8) * BN + col) = v1;
    }
}

// ---------------- SpMM aggregation: out[n] = relu(sum_e val*support[col] + b) ----------------
__global__ __launch_bounds__(128) void agg_kernel(
    const float* __restrict__ support, const int* __restrict__ rowptr,
    const int* __restrict__ ecol, const float* __restrict__ eval,
    const float* __restrict__ bias, float* __restrict__ out)
{
    const int node = blockIdx.x;
    const int d = threadIdx.x;
    const int s = __ldg(&rowptr[node]);
    const int e = __ldg(&rowptr[node + 1]);
    float acc = 0.f;
    for (int i = s; i < e; i++) {
        int c = __ldg(&ecol[i]);
        float v = __ldg(&eval[i]);
        acc += v * __ldg(&support[(size_t)c * 128 + d]);
    }
    out[(size_t)node * 128 + d] = fmaxf(acc + __ldg(&bias[d]), 0.f);
}

// ---------------- final tiny layer ----------------
__global__ void mlp3_kernel(const float* __restrict__ h2, const float* __restrict__ W,
                            const float* __restrict__ b, float* __restrict__ out, int M)
{
    int n = blockIdx.x * blockDim.x + threadIdx.x;
    if (n >= M) return;
    float s0 = __ldg(&b[0]);
    float s1 = __ldg(&b[1]);
    const float* h = h2 + (size_t)n * 64;
    #pragma unroll
    for (int k4 = 0; k4 < 16; k4++) {
        float4 hv = *(const float4*)(h + 4 * k4);
        float4 w0, w1;
        w0.x = __ldg(&W[(4 * k4 + 0) * 2 + 0]); w1.x = __ldg(&W[(4 * k4 + 0) * 2 + 1]);
        w0.y = __ldg(&W[(4 * k4 + 1) * 2 + 0]); w1.y = __ldg(&W[(4 * k4 + 1) * 2 + 1]);
        w0.z = __ldg(&W[(4 * k4 + 2) * 2 + 0]); w1.z = __ldg(&W[(4 * k4 + 2) * 2 + 1]);
        w0.w = __ldg(&W[(4 * k4 + 3) * 2 + 0]); w1.w = __ldg(&W[(4 * k4 + 3) * 2 + 1]);
        s0 += hv.x * w0.x + hv.y * w0.y + hv.z * w0.z + hv.w * w0.w;
        s1 += hv.x * w1.x + hv.y * w1.y + hv.z * w1.z + hv.w * w1.w;
    }
    out[2 * n + 0] = s0;
    out[2 * n + 1] = s1;
}

// ---------------- launch ----------------
static void* sym_addr(const void* symbol) {
    void* p = nullptr;
    cudaGetSymbolAddress(&p, symbol);
    return p;
}

extern "C" void kernel_launch(void* const* d_in, const int* in_sizes, int n_in,
                              void* d_out, int out_size) {
    const int*   adj_row = (const int*)d_in[0];
    const int*   adj_col = (const int*)d_in[1];
    const float* adj_val = (const float*)d_in[2];
    const float* xin     = (const float*)d_in[3];
    const float* W1 = (const float*)d_in[5];
    const float* b1 = (const float*)d_in[6];
    const float* W2 = (const float*)d_in[7];
    const float* b2 = (const float*)d_in[8];
    const float* W3 = (const float*)d_in[9];
    const float* b3 = (const float*)d_in[10];
    const float* fcW1 = (const float*)d_in[11];
    const float* fcb1 = (const float*)d_in[12];
    const float* fcW2 = (const float*)d_in[13];
    const float* fcb2 = (const float*)d_in[14];
    const float* fcW3 = (const float*)d_in[15];
    const float* fcb3 = (const float*)d_in[16];

    const int E = in_sizes[0];
    const int M = in_sizes[4];

    int*   cnt     = (int*)sym_addr(g_cnt);
    int*   rowptr  = (int*)sym_addr(g_rowptr);
    int*   woff    = (int*)sym_addr(g_woff);
    int*   ecol    = (int*)sym_addr(g_ecol);
    float* eval    = (float*)sym_addr(g_eval);
    float* support = (float*)sym_addr(g_support);
    float* gg1     = (float*)sym_addr(g_g1);
    float* gg2     = (float*)sym_addr(g_g2);
    float* gg3     = (float*)sym_addr(g_g3);
    float* h1      = (float*)sym_addr(g_h1);
    float* h2      = (float*)sym_addr(g_h2);
    __nv_bfloat16* wthi = (__nv_bfloat16*)sym_addr(g_wthi);
    __nv_bfloat16* wtlo = (__nv_bfloat16*)sym_addr(g_wtlo);
    float* out     = (float*)d_out;

    constexpr int A_BYTES = 128 * 272;                       // 34816
    const int SMEM128 = 2 * A_BYTES + 2 * 128 * 272;         // 139264
    const int SMEM64  = 2 * A_BYTES + 2 * 64 * 272;          // 104448
    cudaFuncSetAttribute(gemm_mma<128, 1, false>, cudaFuncAttributeMaxDynamicSharedMemorySize, SMEM128);
    cudaFuncSetAttribute(gemm_mma<128, 3, true>,  cudaFuncAttributeMaxDynamicSharedMemorySize, SMEM128);
    cudaFuncSetAttribute(gemm_mma<64, 1, true>,   cudaFuncAttributeMaxDynamicSharedMemorySize, SMEM64);

    const int gb = (M + 127) / 128;

    // CSR build
    zero_cnt_kernel<<<(M + 255) / 256, 256>>>(cnt, M);
    hist_kernel<<<(E + 255) / 256, 256>>>(adj_row, cnt, E);
    scan_kernel<<<1, 1024>>>(cnt, rowptr, woff, M);
    scatter_kernel<<<(E + 255) / 256, 256>>>(adj_row, adj_col, adj_val, woff, ecol, eval, E);

    // GCN layer 1
    wsplit_kernel<<<(128 * 128 + 255) / 256, 256>>>(W1, wthi, wtlo, 128, 128);
    gemm_mma<128, 1, false><<<gb, 256, SMEM128>>>(xin, nullptr, nullptr, wthi, wtlo, nullptr, support, M);
    agg_kernel<<<M, 128>>>(support, rowptr, ecol, eval, b1, gg1);
    // GCN layer 2
    wsplit_kernel<<<(128 * 128 + 255) / 256, 256>>>(W2, wthi, wtlo, 128, 128);
    gemm_mma<128, 1, false><<<gb, 256, SMEM128>>>(gg1, nullptr, nullptr, wthi, wtlo, nullptr, support, M);
    agg_kernel<<<M, 128>>>(support, rowptr, ecol, eval, b2, gg2);
    // GCN layer 3
    wsplit_kernel<<<(128 * 128 + 255) / 256, 256>>>(W3, wthi, wtlo, 128, 128);
    gemm_mma<128, 1, false><<<gb, 256, SMEM128>>>(gg2, nullptr, nullptr, wthi, wtlo, nullptr, support, M);
    agg_kernel<<<M, 128>>>(support, rowptr, ecol, eval, b3, gg3);

    // fc1: [g1|g2|g3] @ fcW1 (K=384), bias+relu
    wsplit_kernel<<<(384 * 128 + 255) / 256, 256>>>(fcW1, wthi, wtlo, 384, 128);
    gemm_mma<128, 3, true><<<gb, 256, SMEM128>>>(gg1, gg2, gg3, wthi, wtlo, fcb1, h1, M);
    // fc2: h1 @ fcW2 (N=64), bias+relu
    wsplit_kernel<<<(128 * 64 + 255) / 256, 256>>>(fcW2, wthi, wtlo, 128, 64);
    gemm_mma<64, 1, true><<<gb, 256, SMEM64>>>(h1, nullptr, nullptr, wthi, wtlo, fcb2, h2, M);
    // fc3 tiny
    mlp3_kernel<<<(M + 255) / 256, 256>>>(h2, fcW3, fcb3, out, M);
}

// round 11
// speedup vs baseline: 1.7568x; 1.3478x over previous
#include <cuda_runtime.h>
#include <cuda_bf16.h>
#include <cstdint>

// Problem constants
#define NN 50000
#define NE 800000

// ---------------- device scratch (static, no allocation) ----------------
__device__ int   g_cnt[NN];
__device__ int   g_rowptr[NN + 1];
__device__ int   g_woff[NN];
__device__ int   g_ecol[NE];
__device__ float g_eval[NE];
__device__ float g_support[(size_t)NN * 128];
__device__ float g_g1[(size_t)NN * 128];
__device__ float g_g2[(size_t)NN * 128];
__device__ float g_g3[(size_t)NN * 128];
__device__ float g_h1[(size_t)NN * 128];
__device__ float g_h2[(size_t)NN * 64];
// per-layer transposed/split weights (no false deps between layers)
__device__ __nv_bfloat16 g_w1hi[128 * 128], g_w1lo[128 * 128];
__device__ __nv_bfloat16 g_w2hi[128 * 128], g_w2lo[128 * 128];
__device__ __nv_bfloat16 g_w3hi[128 * 128], g_w3lo[128 * 128];
__device__ __nv_bfloat16 g_f1hi[128 * 384], g_f1lo[128 * 384];
__device__ __nv_bfloat16 g_f2hi[64 * 128],  g_f2lo[64 * 128];

// ---------------- helpers ----------------
__device__ __forceinline__ uint32_t smem_u32(const void* p) {
    uint32_t a;
    asm("{ .reg .u64 t; cvta.to.shared.u64 t, %1; cvt.u32.u64 %0, t; }" : "=r"(a) : "l"(p));
    return a;
}

#define LDSM4(r, addr) \
    asm volatile("ldmatrix.sync.aligned.m8n8.x4.shared.b16 {%0,%1,%2,%3}, [%4];" \
        : "=r"((r)[0]), "=r"((r)[1]), "=r"((r)[2]), "=r"((r)[3]) : "r"(addr))

#define MMA16816(d, a, b0, b1) \
    asm volatile("mma.sync.aligned.m16n8k16.row.col.f32.bf16.bf16.f32 " \
        "{%0,%1,%2,%3}, {%4,%5,%6,%7}, {%8,%9}, {%0,%1,%2,%3};" \
        : "+f"((d)[0]), "+f"((d)[1]), "+f"((d)[2]), "+f"((d)[3]) \
        : "r"((a)[0]), "r"((a)[1]), "r"((a)[2]), "r"((a)[3]), "r"(b0), "r"(b1))

// ---------------- CSR build ----------------
__global__ void zero_cnt_kernel(int* __restrict__ cnt, int n) {
    int i = blockIdx.x * blockDim.x + threadIdx.x;
    if (i < n) cnt[i] = 0;
}

__global__ void hist_kernel(const int* __restrict__ row, int* __restrict__ cnt, int e) {
    int i = blockIdx.x * blockDim.x + threadIdx.x;
    if (i < e) atomicAdd(&cnt[row[i]], 1);
}

__global__ void scan_kernel(const int* __restrict__ cnt, int* __restrict__ rowptr,
                            int* __restrict__ woff, int n) {
    __shared__ int warp_sums[32];
    __shared__ int s_carry;
    int tid = threadIdx.x, lane = tid & 31, wid = tid >> 5;
    if (tid == 0) s_carry = 0;
    __syncthreads();
    for (int base = 0; base < n; base += 1024) {
        int carry = s_carry;
        int idx = base + tid;
        int x = (idx < n) ? cnt[idx] : 0;
        int v = x;
        #pragma unroll
        for (int off = 1; off < 32; off <<= 1) {
            int y = __shfl_up_sync(0xffffffffu, v, off);
            if (lane >= off) v += y;
        }
        if (lane == 31) warp_sums[wid] = v;
        __syncthreads();
        if (wid == 0) {
            int w = warp_sums[lane];
            #pragma unroll
            for (int off = 1; off < 32; off <<= 1) {
                int y = __shfl_up_sync(0xffffffffu, w, off);
                if (lane >= off) w += y;
            }
            warp_sums[lane] = w;
        }
        __syncthreads();
        int woffs = (wid > 0) ? warp_sums[wid - 1] : 0;
        int incl = v + woffs;
        if (idx < n) {
            int e = carry + incl - x;
            rowptr[idx] = e;
            woff[idx] = e;
        }
        __syncthreads();
        if (tid == 1023) s_carry = carry + incl;
        __syncthreads();
    }
    if (threadIdx.x == 0) rowptr[n] = s_carry;
}

__global__ void scatter_kernel(const int* __restrict__ row, const int* __restrict__ col,
                               const float* __restrict__ vals, int* __restrict__ woff,
                               int* __restrict__ ecol, float* __restrict__ eval, int e) {
    int i = blockIdx.x * blockDim.x + threadIdx.x;
    if (i < e) {
        int r = row[i];
        int p = atomicAdd(&woff[r], 1);
        ecol[p] = col[i];
        eval[p] = vals[i];
    }
}

// ---------------- weight transpose + bf16 split: W[K][N] -> WT hi/lo [N][K] ----------------
__global__ void wsplit_kernel(const float* __restrict__ W, __nv_bfloat16* __restrict__ hiT,
                              __nv_bfloat16* __restrict__ loT, int K, int N) {
    int i = blockIdx.x * blockDim.x + threadIdx.x;
    if (i >= K * N) return;
    int k = i / N, n = i % N;
    float v = W[i];
    __nv_bfloat16 h = __float2bfloat16(v);
    float r = v - __bfloat162float(h);
    hiT[n * K + k] = h;
    loT[n * K + k] = __float2bfloat16(r);
}

// ---------------- HMMA GEMM: out[M x BN] = relu?(X[M x 128*NCHUNK] @ WT^T + bias) ----------------
// BM=128, 256 threads (8 warps x 16 rows). bf16 split: D = Ahi*Bhi + Ahi*Blo + Alo*Bhi.
// smem rows padded to 136 bf16 (272 B = 17 x 16B) -> conflict-free ldmatrix.
template <int BN, int NCHUNK, bool RELU>
__global__ __launch_bounds__(256, 1)
void gemm_mma(const float* __restrict__ x0, const float* __restrict__ x1,
              const float* __restrict__ x2,
              const __nv_bfloat16* __restrict__ WThi, const __nv_bfloat16* __restrict__ WTlo,
              const float* __restrict__ bias, float* __restrict__ out, int M)
{
    extern __shared__ char smem[];
    constexpr int LDAB = 272;                 // bytes per smem row
    constexpr int A_BYTES = 128 * LDAB;       // 34816
    constexpr int B_BYTES = BN * LDAB;
    char* pAhi = smem;
    char* pAlo = smem + A_BYTES;
    char* pBhi = smem + 2 * A_BYTES;
    char* pBlo = smem + 2 * A_BYTES + B_BYTES;

    const int tid = threadIdx.x, wid = tid >> 5, lane = tid & 31;
    const int m0 = blockIdx.x * 128;
    const int Ktot = NCHUNK * 128;
    constexpr int NT = BN / 8;

    float acc[NT][4];
    #pragma unroll
    for (int t = 0; t < NT; t++)
        #pragma unroll
        for (int j = 0; j < 4; j++) acc[t][j] = 0.f;

    const uint32_t sb = smem_u32(smem);
    const int mat = lane >> 3, r8 = lane & 7;
    const uint32_t a_hi_base = sb + LDAB * (wid * 16 + (mat & 1) * 8 + r8) + 16 * (mat >> 1);
    const uint32_t a_lo_base = a_hi_base + A_BYTES;
    const uint32_t b_hi_base = sb + 2 * A_BYTES + LDAB * ((mat >> 1) * 8 + r8) + 16 * (mat & 1);
    const uint32_t b_lo_base = b_hi_base + B_BYTES;

    const float* srcs[3] = { x0, x1, x2 };

    for (int c = 0; c < NCHUNK; c++) {
        if (c > 0) __syncthreads();
        const float* xs = srcs[c];
        // stage A: 128 x 128 fp32 -> bf16 hi/lo, row-major padded
        #pragma unroll
        for (int i = 0; i < 16; i++) {
            int f = tid + 256 * i;
            int row = f >> 5;
            int col = (f & 31) * 4;
            float4 v = make_float4(0.f, 0.f, 0.f, 0.f);
            int gm = m0 + row;
            if (gm < M) v = *(const float4*)(xs + (size_t)gm * 128 + col);
            __nv_bfloat162 h01 = __floats2bfloat162_rn(v.x, v.y);
            __nv_bfloat162 h23 = __floats2bfloat162_rn(v.z, v.w);
            __nv_bfloat162 l01 = __floats2bfloat162_rn(v.x - __bfloat162float(h01.x),
                                                       v.y - __bfloat162float(h01.y));
            __nv_bfloat162 l23 = __floats2bfloat162_rn(v.z - __bfloat162float(h23.x),
                                                       v.w - __bfloat162float(h23.y));
            int off = LDAB * row + 2 * col;
            *(__nv_bfloat162*)(pAhi + off)     = h01;
            *(__nv_bfloat162*)(pAhi + off + 4) = h23;
            *(__nv_bfloat162*)(pAlo + off)     = l01;
            *(__nv_bfloat162*)(pAlo + off + 4) = l23;
        }
        // stage B: BN x 128 bf16 hi/lo from WT [N][Ktot]
        #pragma unroll
        for (int i = 0; i < BN / 16; i++) {
            int f = tid + 256 * i;
            int row = f >> 4;
            int col = (f & 15) * 8;
            uint4 vh = *(const uint4*)(WThi + (size_t)row * Ktot + c * 128 + col);
            uint4 vl = *(const uint4*)(WTlo + (size_t)row * Ktot + c * 128 + col);
            int off = LDAB * row + 2 * col;
            *(uint4*)(pBhi + off) = vh;
            *(uint4*)(pBlo + off) = vl;
        }
        __syncthreads();

        #pragma unroll
        for (int ks = 0; ks < 8; ks++) {
            uint32_t ah[4], al[4];
            LDSM4(ah, a_hi_base + 32 * ks);
            LDSM4(al, a_lo_base + 32 * ks);
            #pragma unroll
            for (int np = 0; np < NT / 2; np++) {
                uint32_t bh[4], bl[4];
                LDSM4(bh, b_hi_base + 16 * LDAB * np + 32 * ks);
                LDSM4(bl, b_lo_base + 16 * LDAB * np + 32 * ks);
                MMA16816(acc[2 * np],     ah, bh[0], bh[1]);
                MMA16816(acc[2 * np],     ah, bl[0], bl[1]);
                MMA16816(acc[2 * np],     al, bh[0], bh[1]);
                MMA16816(acc[2 * np + 1], ah, bh[2], bh[3]);
                MMA16816(acc[2 * np + 1], ah, bl[2], bl[3]);
                MMA16816(acc[2 * np + 1], al, bh[2], bh[3]);
            }
        }
    }

    // epilogue: D frag -> rows (wid*16 + lane>>2) and +8, cols 8t + (lane&3)*2
    const int row0 = m0 + wid * 16 + (lane >> 2);
    const int coff = (lane & 3) * 2;
    #pragma unroll
    for (int t = 0; t < NT; t++) {
        int col = 8 * t + coff;
        float b0 = 0.f, b1 = 0.f;
        if (bias != nullptr) { b0 = __ldg(&bias[col]); b1 = __ldg(&bias[col + 1]); }
        float2 v0 = make_float2(acc[t][0] + b0, acc[t][1] + b1);
        float2 v1 = make_float2(acc[t][2] + b0, acc[t][3] + b1);
        if (RELU) {
            v0.x = fmaxf(v0.x, 0.f); v0.y = fmaxf(v0.y, 0.f);
            v1.x = fmaxf(v1.x, 0.f); v1.y = fmaxf(v1.y, 0.f);
        }
        if (row0 < M)     *(float2*)(out + (size_t)row0 * BN + col) = v0;
        if (row0 + 8 < M) *(float2*)(out + (size_t)(row0 + 8) * BN + col) = v1;
    }
}

// ---------------- SpMM aggregation: warp per node, float4 per lane ----------------
// out[n][:] = relu(sum_e val[e] * support[col[e]][:] + bias)
__global__ __launch_bounds__(128) void agg_kernel(
    const float4* __restrict__ support4, const int* __restrict__ rowptr,
    const int* __restrict__ ecol, const float* __restrict__ eval,
    const float4* __restrict__ bias4, float4* __restrict__ out4, int M)
{
    const int node = blockIdx.x * 4 + (threadIdx.x >> 5);
    const int lane = threadIdx.x & 31;
    if (node >= M) return;
    const int s = __ldg(&rowptr[node]);
    const int e = __ldg(&rowptr[node + 1]);
    float4 acc = make_float4(0.f, 0.f, 0.f, 0.f);
    int i = s;
    for (; i + 1 < e; i += 2) {
        int c0 = __ldg(&ecol[i]);
        int c1 = __ldg(&ecol[i + 1]);
        float v0 = __ldg(&eval[i]);
        float v1 = __ldg(&eval[i + 1]);
        float4 s0 = __ldg(&support4[(size_t)c0 * 32 + lane]);
        float4 s1 = __ldg(&support4[(size_t)c1 * 32 + lane]);
        acc.x += v0 * s0.x + v1 * s1.x;
        acc.y += v0 * s0.y + v1 * s1.y;
        acc.z += v0 * s0.z + v1 * s1.z;
        acc.w += v0 * s0.w + v1 * s1.w;
    }
    if (i < e) {
        int c0 = __ldg(&ecol[i]);
        float v0 = __ldg(&eval[i]);
        float4 s0 = __ldg(&support4[(size_t)c0 * 32 + lane]);
        acc.x += v0 * s0.x;
        acc.y += v0 * s0.y;
        acc.z += v0 * s0.z;
        acc.w += v0 * s0.w;
    }
    float4 b = __ldg(&bias4[lane]);
    float4 o;
    o.x = fmaxf(acc.x + b.x, 0.f);
    o.y = fmaxf(acc.y + b.y, 0.f);
    o.z = fmaxf(acc.z + b.z, 0.f);
    o.w = fmaxf(acc.w + b.w, 0.f);
    out4[(size_t)node * 32 + lane] = o;
}

// ---------------- final tiny layer ----------------
__global__ void mlp3_kernel(const float* __restrict__ h2, const float* __restrict__ W,
                            const float* __restrict__ b, float* __restrict__ out, int M)
{
    int n = blockIdx.x * blockDim.x + threadIdx.x;
    if (n >= M) return;
    float s0 = __ldg(&b[0]);
    float s1 = __ldg(&b[1]);
    const float* h = h2 + (size_t)n * 64;
    #pragma unroll
    for (int k4 = 0; k4 < 16; k4++) {
        float4 hv = *(const float4*)(h + 4 * k4);
        float4 w0, w1;
        w0.x = __ldg(&W[(4 * k4 + 0) * 2 + 0]); w1.x = __ldg(&W[(4 * k4 + 0) * 2 + 1]);
        w0.y = __ldg(&W[(4 * k4 + 1) * 2 + 0]); w1.y = __ldg(&W[(4 * k4 + 1) * 2 + 1]);
        w0.z = __ldg(&W[(4 * k4 + 2) * 2 + 0]); w1.z = __ldg(&W[(4 * k4 + 2) * 2 + 1]);
        w0.w = __ldg(&W[(4 * k4 + 3) * 2 + 0]); w1.w = __ldg(&W[(4 * k4 + 3) * 2 + 1]);
        s0 += hv.x * w0.x + hv.y * w0.y + hv.z * w0.z + hv.w * w0.w;
        s1 += hv.x * w1.x + hv.y * w1.y + hv.z * w1.z + hv.w * w1.w;
    }
    out[2 * n + 0] = s0;
    out[2 * n + 1] = s1;
}

// ---------------- launch ----------------
static void* sym_addr(const void* symbol) {
    void* p = nullptr;
    cudaGetSymbolAddress(&p, symbol);
    return p;
}

extern "C" void kernel_launch(void* const* d_in, const int* in_sizes, int n_in,
                              void* d_out, int out_size) {
    const int*   adj_row = (const int*)d_in[0];
    const int*   adj_col = (const int*)d_in[1];
    const float* adj_val = (const float*)d_in[2];
    const float* xin     = (const float*)d_in[3];
    const float* W1 = (const float*)d_in[5];
    const float* b1 = (const float*)d_in[6];
    const float* W2 = (const float*)d_in[7];
    const float* b2 = (const float*)d_in[8];
    const float* W3 = (const float*)d_in[9];
    const float* b3 = (const float*)d_in[10];
    const float* fcW1 = (const float*)d_in[11];
    const float* fcb1 = (const float*)d_in[12];
    const float* fcW2 = (const float*)d_in[13];
    const float* fcb2 = (const float*)d_in[14];
    const float* fcW3 = (const float*)d_in[15];
    const float* fcb3 = (const float*)d_in[16];

    const int E = in_sizes[0];
    const int M = in_sizes[4];

    int*   cnt     = (int*)sym_addr(g_cnt);
    int*   rowptr  = (int*)sym_addr(g_rowptr);
    int*   woff    = (int*)sym_addr(g_woff);
    int*   ecol    = (int*)sym_addr(g_ecol);
    float* eval    = (float*)sym_addr(g_eval);
    float* support = (float*)sym_addr(g_support);
    float* gg1     = (float*)sym_addr(g_g1);
    float* gg2     = (float*)sym_addr(g_g2);
    float* gg3     = (float*)sym_addr(g_g3);
    float* h1      = (float*)sym_addr(g_h1);
    float* h2      = (float*)sym_addr(g_h2);
    __nv_bfloat16* w1hi = (__nv_bfloat16*)sym_addr(g_w1hi);
    __nv_bfloat16* w1lo = (__nv_bfloat16*)sym_addr(g_w1lo);
    __nv_bfloat16* w2hi = (__nv_bfloat16*)sym_addr(g_w2hi);
    __nv_bfloat16* w2lo = (__nv_bfloat16*)sym_addr(g_w2lo);
    __nv_bfloat16* w3hi = (__nv_bfloat16*)sym_addr(g_w3hi);
    __nv_bfloat16* w3lo = (__nv_bfloat16*)sym_addr(g_w3lo);
    __nv_bfloat16* f1hi = (__nv_bfloat16*)sym_addr(g_f1hi);
    __nv_bfloat16* f1lo = (__nv_bfloat16*)sym_addr(g_f1lo);
    __nv_bfloat16* f2hi = (__nv_bfloat16*)sym_addr(g_f2hi);
    __nv_bfloat16* f2lo = (__nv_bfloat16*)sym_addr(g_f2lo);
    float* out     = (float*)d_out;

    constexpr int A_BYTES = 128 * 272;                       // 34816
    const int SMEM128 = 2 * A_BYTES + 2 * 128 * 272;         // 139264
    const int SMEM64  = 2 * A_BYTES + 2 * 64 * 272;          // 104448
    cudaFuncSetAttribute(gemm_mma<128, 1, false>, cudaFuncAttributeMaxDynamicSharedMemorySize, SMEM128);
    cudaFuncSetAttribute(gemm_mma<128, 3, true>,  cudaFuncAttributeMaxDynamicSharedMemorySize, SMEM128);
    cudaFuncSetAttribute(gemm_mma<64, 1, true>,   cudaFuncAttributeMaxDynamicSharedMemorySize, SMEM64);

    // lazy one-time creation of side stream + events (host resources only; the
    // captured work is identical on every call)
    static cudaStream_t s_side = nullptr;
    static cudaEvent_t ev_root = nullptr, ev_csr = nullptr;
    if (s_side == nullptr) {
        cudaStreamCreateWithFlags(&s_side, cudaStreamNonBlocking);
        cudaEventCreateWithFlags(&ev_root, cudaEventDisableTiming);
        cudaEventCreateWithFlags(&ev_csr, cudaEventDisableTiming);
    }

    const int gb = (M + 127) / 128;
    const int ab = (M + 3) / 4;

    // ---- fork: CSR build on side stream (independent of GEMM path) ----
    cudaEventRecord(ev_root, 0);
    cudaStreamWaitEvent(s_side, ev_root, 0);
    zero_cnt_kernel<<<(M + 255) / 256, 256, 0, s_side>>>(cnt, M);
    hist_kernel<<<(E + 255) / 256, 256, 0, s_side>>>(adj_row, cnt, E);
    scan_kernel<<<1, 1024, 0, s_side>>>(cnt, rowptr, woff, M);
    scatter_kernel<<<(E + 255) / 256, 256, 0, s_side>>>(adj_row, adj_col, adj_val, woff, ecol, eval, E);
    cudaEventRecord(ev_csr, s_side);

    // ---- main stream: all weight splits (independent), then GEMM1 ----
    wsplit_kernel<<<(128 * 128 + 255) / 256, 256>>>(W1, w1hi, w1lo, 128, 128);
    wsplit_kernel<<<(128 * 128 + 255) / 256, 256>>>(W2, w2hi, w2lo, 128, 128);
    wsplit_kernel<<<(128 * 128 + 255) / 256, 256>>>(W3, w3hi, w3lo, 128, 128);
    wsplit_kernel<<<(384 * 128 + 255) / 256, 256>>>(fcW1, f1hi, f1lo, 384, 128);
    wsplit_kernel<<<(128 * 64 + 255) / 256, 256>>>(fcW2, f2hi, f2lo, 128, 64);

    gemm_mma<128, 1, false><<<gb, 256, SMEM128>>>(xin, nullptr, nullptr, w1hi, w1lo, nullptr, support, M);

    // ---- join: aggregation needs CSR ----
    cudaStreamWaitEvent(0, ev_csr, 0);

    agg_kernel<<<ab, 128>>>((const float4*)support, rowptr, ecol, eval, (const float4*)b1, (float4*)gg1, M);
    gemm_mma<128, 1, false><<<gb, 256, SMEM128>>>(gg1, nullptr, nullptr, w2hi, w2lo, nullptr, support, M);
    agg_kernel<<<ab, 128>>>((const float4*)support, rowptr, ecol, eval, (const float4*)b2, (float4*)gg2, M);
    gemm_mma<128, 1, false><<<gb, 256, SMEM128>>>(gg2, nullptr, nullptr, w3hi, w3lo, nullptr, support, M);
    agg_kernel<<<ab, 128>>>((const float4*)support, rowptr, ecol, eval, (const float4*)b3, (float4*)gg3, M);

    // fc1: [g1|g2|g3] @ fcW1 (K=384), bias+relu
    gemm_mma<128, 3, true><<<gb, 256, SMEM128>>>(gg1, gg2, gg3, f1hi, f1lo, fcb1, h1, M);
    // fc2: h1 @ fcW2 (N=64), bias+relu
    gemm_mma<64, 1, true><<<gb, 256, SMEM64>>>(h1, nullptr, nullptr, f2hi, f2lo, fcb2, h2, M);
    // fc3 tiny
    mlp3_kernel<<<(M + 255) / 256, 256>>>(h2, fcW3, fcb3, out, M);
}

// round 12
// speedup vs baseline: 1.9737x; 1.1234x over previous
#include <cuda_runtime.h>
#include <cuda_bf16.h>
#include <cstdint>

// Problem constants
#define NN 50000
#define NE 800000

// ---------------- device scratch (static, no allocation) ----------------
__device__ int   g_cnt[NN];
__device__ int   g_rowptr[NN + 1];
__device__ int   g_woff[NN];
__device__ int   g_ecol[NE];
__device__ float g_eval[NE];
__device__ float g_support[(size_t)NN * 128];
__device__ float g_g1[(size_t)NN * 128];
__device__ float g_g2[(size_t)NN * 128];
__device__ float g_g3[(size_t)NN * 128];
__device__ float g_h1[(size_t)NN * 128];
__device__ float g_h2[(size_t)NN * 64];
// per-layer transposed/split weights
__device__ __nv_bfloat16 g_w1hi[128 * 128], g_w1lo[128 * 128];
__device__ __nv_bfloat16 g_w2hi[128 * 128], g_w2lo[128 * 128];
__device__ __nv_bfloat16 g_w3hi[128 * 128], g_w3lo[128 * 128];
__device__ __nv_bfloat16 g_f1hi[128 * 384], g_f1lo[128 * 384];
__device__ __nv_bfloat16 g_f2hi[64 * 128],  g_f2lo[64 * 128];

// ---------------- helpers ----------------
__device__ __forceinline__ uint32_t smem_u32(const void* p) {
    uint32_t a;
    asm("{ .reg .u64 t; cvta.to.shared.u64 t, %1; cvt.u32.u64 %0, t; }" : "=r"(a) : "l"(p));
    return a;
}

#define LDSM4(r, addr) \
    asm volatile("ldmatrix.sync.aligned.m8n8.x4.shared.b16 {%0,%1,%2,%3}, [%4];" \
        : "=r"((r)[0]), "=r"((r)[1]), "=r"((r)[2]), "=r"((r)[3]) : "r"(addr))

#define MMA16816(d, a, b0, b1) \
    asm volatile("mma.sync.aligned.m16n8k16.row.col.f32.bf16.bf16.f32 " \
        "{%0,%1,%2,%3}, {%4,%5,%6,%7}, {%8,%9}, {%0,%1,%2,%3};" \
        : "+f"((d)[0]), "+f"((d)[1]), "+f"((d)[2]), "+f"((d)[3]) \
        : "r"((a)[0]), "r"((a)[1]), "r"((a)[2]), "r"((a)[3]), "r"(b0), "r"(b1))

// ---------------- CSR build ----------------
__global__ void zero_cnt_kernel(int* __restrict__ cnt, int n) {
    int i = blockIdx.x * blockDim.x + threadIdx.x;
    if (i < n) cnt[i] = 0;
}

__global__ void hist_kernel(const int* __restrict__ row, int* __restrict__ cnt, int e) {
    int i = blockIdx.x * blockDim.x + threadIdx.x;
    if (i < e) atomicAdd(&cnt[row[i]], 1);
}

__global__ void scan_kernel(const int* __restrict__ cnt, int* __restrict__ rowptr,
                            int* __restrict__ woff, int n) {
    __shared__ int warp_sums[32];
    __shared__ int s_carry;
    int tid = threadIdx.x, lane = tid & 31, wid = tid >> 5;
    if (tid == 0) s_carry = 0;
    __syncthreads();
    for (int base = 0; base < n; base += 1024) {
        int carry = s_carry;
        int idx = base + tid;
        int x = (idx < n) ? cnt[idx] : 0;
        int v = x;
        #pragma unroll
        for (int off = 1; off < 32; off <<= 1) {
            int y = __shfl_up_sync(0xffffffffu, v, off);
            if (lane >= off) v += y;
        }
        if (lane == 31) warp_sums[wid] = v;
        __syncthreads();
        if (wid == 0) {
            int w = warp_sums[lane];
            #pragma unroll
            for (int off = 1; off < 32; off <<= 1) {
                int y = __shfl_up_sync(0xffffffffu, w, off);
                if (lane >= off) w += y;
            }
            warp_sums[lane] = w;
        }
        __syncthreads();
        int woffs = (wid > 0) ? warp_sums[wid - 1] : 0;
        int incl = v + woffs;
        if (idx < n) {
            int e = carry + incl - x;
            rowptr[idx] = e;
            woff[idx] = e;
        }
        __syncthreads();
        if (tid == 1023) s_carry = carry + incl;
        __syncthreads();
    }
    if (threadIdx.x == 0) rowptr[n] = s_carry;
}

__global__ void scatter_kernel(const int* __restrict__ row, const int* __restrict__ col,
                               const float* __restrict__ vals, int* __restrict__ woff,
                               int* __restrict__ ecol, float* __restrict__ eval, int e) {
    int i = blockIdx.x * blockDim.x + threadIdx.x;
    if (i < e) {
        int r = row[i];
        int p = atomicAdd(&woff[r], 1);
        ecol[p] = col[i];
        eval[p] = vals[i];
    }
}

// ---------------- fused weight transpose + bf16 split for all 5 matrices ----------------
// W[K][N] -> WT hi/lo [N][K]
__device__ __forceinline__ void wsplit_one(const float* __restrict__ W,
                                           __nv_bfloat16* __restrict__ hiT,
                                           __nv_bfloat16* __restrict__ loT,
                                           int j, int K, int N) {
    int k = j / N, n = j % N;
    float v = W[j];
    __nv_bfloat16 h = __float2bfloat16(v);
    float r = v - __bfloat162float(h);
    hiT[n * K + k] = h;
    loT[n * K + k] = __float2bfloat16(r);
}

__global__ void wsplit_all_kernel(
    const float* __restrict__ W1, const float* __restrict__ W2, const float* __restrict__ W3,
    const float* __restrict__ F1, const float* __restrict__ F2,
    __nv_bfloat16* __restrict__ w1hi, __nv_bfloat16* __restrict__ w1lo,
    __nv_bfloat16* __restrict__ w2hi, __nv_bfloat16* __restrict__ w2lo,
    __nv_bfloat16* __restrict__ w3hi, __nv_bfloat16* __restrict__ w3lo,
    __nv_bfloat16* __restrict__ f1hi, __nv_bfloat16* __restrict__ f1lo,
    __nv_bfloat16* __restrict__ f2hi, __nv_bfloat16* __restrict__ f2lo)
{
    int i = blockIdx.x * blockDim.x + threadIdx.x;
    // segments: 3x 16384 (W1..W3), 49152 (F1), 8192 (F2) -> total 106496
    if (i < 16384)       wsplit_one(W1, w1hi, w1lo, i, 128, 128);
    else if (i < 32768)  wsplit_one(W2, w2hi, w2lo, i - 16384, 128, 128);
    else if (i < 49152)  wsplit_one(W3, w3hi, w3lo, i - 32768, 128, 128);
    else if (i < 98304)  wsplit_one(F1, f1hi, f1lo, i - 49152, 384, 128);
    else if (i < 106496) wsplit_one(F2, f2hi, f2lo, i - 98304, 128, 64);
}

// ---------------- HMMA GEMM: out[M x BN] (+)= relu?(X[M x 128*NCHUNK] @ WT^T + bias) ----------------
// BM=128, 256 threads (8 warps x 16 rows). bf16 split: D = Ahi*Bhi + Ahi*Blo + Alo*Bhi.
// smem rows padded to 136 bf16 (272 B) -> conflict-free ldmatrix.
// wt_stride: row stride (elements) of the WT hi/lo buffers (supports K-chunk slices).
template <int BN, int NCHUNK, bool RELU, bool ACCUM>
__global__ __launch_bounds__(256, 1)
void gemm_mma(const float* __restrict__ x0, const float* __restrict__ x1,
              const float* __restrict__ x2,
              const __nv_bfloat16* __restrict__ WThi, const __nv_bfloat16* __restrict__ WTlo,
              const float* __restrict__ bias, float* __restrict__ out, int M, int wt_stride)
{
    extern __shared__ char smem[];
    constexpr int LDAB = 272;                 // bytes per smem row
    constexpr int A_BYTES = 128 * LDAB;       // 34816
    constexpr int B_BYTES = BN * LDAB;
    char* pAhi = smem;
    char* pAlo = smem + A_BYTES;
    char* pBhi = smem + 2 * A_BYTES;
    char* pBlo = smem + 2 * A_BYTES + B_BYTES;

    const int tid = threadIdx.x, wid = tid >> 5, lane = tid & 31;
    const int m0 = blockIdx.x * 128;
    constexpr int NT = BN / 8;

    float acc[NT][4];
    #pragma unroll
    for (int t = 0; t < NT; t++)
        #pragma unroll
        for (int j = 0; j < 4; j++) acc[t][j] = 0.f;

    const uint32_t sb = smem_u32(smem);
    const int mat = lane >> 3, r8 = lane & 7;
    const uint32_t a_hi_base = sb + LDAB * (wid * 16 + (mat & 1) * 8 + r8) + 16 * (mat >> 1);
    const uint32_t a_lo_base = a_hi_base + A_BYTES;
    const uint32_t b_hi_base = sb + 2 * A_BYTES + LDAB * ((mat >> 1) * 8 + r8) + 16 * (mat & 1);
    const uint32_t b_lo_base = b_hi_base + B_BYTES;

    const float* srcs[3] = { x0, x1, x2 };

    for (int c = 0; c < NCHUNK; c++) {
        if (c > 0) __syncthreads();
        const float* xs = srcs[c];
        // stage A: 128 x 128 fp32 -> bf16 hi/lo, row-major padded
        #pragma unroll
        for (int i = 0; i < 16; i++) {
            int f = tid + 256 * i;
            int row = f >> 5;
            int col = (f & 31) * 4;
            float4 v = make_float4(0.f, 0.f, 0.f, 0.f);
            int gm = m0 + row;
            if (gm < M) v = *(const float4*)(xs + (size_t)gm * 128 + col);
            __nv_bfloat162 h01 = __floats2bfloat162_rn(v.x, v.y);
            __nv_bfloat162 h23 = __floats2bfloat162_rn(v.z, v.w);
            __nv_bfloat162 l01 = __floats2bfloat162_rn(v.x - __bfloat162float(h01.x),
                                                       v.y - __bfloat162float(h01.y));
            __nv_bfloat162 l23 = __floats2bfloat162_rn(v.z - __bfloat162float(h23.x),
                                                       v.w - __bfloat162float(h23.y));
            int off = LDAB * row + 2 * col;
            *(__nv_bfloat162*)(pAhi + off)     = h01;
            *(__nv_bfloat162*)(pAhi + off + 4) = h23;
            *(__nv_bfloat162*)(pAlo + off)     = l01;
            *(__nv_bfloat162*)(pAlo + off + 4) = l23;
        }
        // stage B: BN x 128 bf16 hi/lo from WT [N][wt_stride]
        #pragma unroll
        for (int i = 0; i < BN / 16; i++) {
            int f = tid + 256 * i;
            int row = f >> 4;
            int col = (f & 15) * 8;
            uint4 vh = *(const uint4*)(WThi + (size_t)row * wt_stride + c * 128 + col);
            uint4 vl = *(const uint4*)(WTlo + (size_t)row * wt_stride + c * 128 + col);
            int off = LDAB * row + 2 * col;
            *(uint4*)(pBhi + off) = vh;
            *(uint4*)(pBlo + off) = vl;
        }
        __syncthreads();

        #pragma unroll
        for (int ks = 0; ks < 8; ks++) {
            uint32_t ah[4], al[4];
            LDSM4(ah, a_hi_base + 32 * ks);
            LDSM4(al, a_lo_base + 32 * ks);
            #pragma unroll
            for (int np = 0; np < NT / 2; np++) {
                uint32_t bh[4], bl[4];
                LDSM4(bh, b_hi_base + 16 * LDAB * np + 32 * ks);
                LDSM4(bl, b_lo_base + 16 * LDAB * np + 32 * ks);
                MMA16816(acc[2 * np],     ah, bh[0], bh[1]);
                MMA16816(acc[2 * np],     ah, bl[0], bl[1]);
                MMA16816(acc[2 * np],     al, bh[0], bh[1]);
                MMA16816(acc[2 * np + 1], ah, bh[2], bh[3]);
                MMA16816(acc[2 * np + 1], ah, bl[2], bl[3]);
                MMA16816(acc[2 * np + 1], al, bh[2], bh[3]);
            }
        }
    }

    // epilogue: D frag -> rows (wid*16 + lane>>2) and +8, cols 8t + (lane&3)*2
    const int row0 = m0 + wid * 16 + (lane >> 2);
    const int coff = (lane & 3) * 2;
    #pragma unroll
    for (int t = 0; t < NT; t++) {
        int col = 8 * t + coff;
        float b0 = 0.f, b1 = 0.f;
        if (bias != nullptr) { b0 = __ldg(&bias[col]); b1 = __ldg(&bias[col + 1]); }
        float2 v0 = make_float2(acc[t][0] + b0, acc[t][1] + b1);
        float2 v1 = make_float2(acc[t][2] + b0, acc[t][3] + b1);
        if (ACCUM) {
            if (row0 < M) {
                float2 p = *(const float2*)(out + (size_t)row0 * BN + col);
                v0.x += p.x; v0.y += p.y;
            }
            if (row0 + 8 < M) {
                float2 p = *(const float2*)(out + (size_t)(row0 + 8) * BN + col);
                v1.x += p.x; v1.y += p.y;
            }
        }
        if (RELU) {
            v0.x = fmaxf(v0.x, 0.f); v0.y = fmaxf(v0.y, 0.f);
            v1.x = fmaxf(v1.x, 0.f); v1.y = fmaxf(v1.y, 0.f);
        }
        if (row0 < M)     *(float2*)(out + (size_t)row0 * BN + col) = v0;
        if (row0 + 8 < M) *(float2*)(out + (size_t)(row0 + 8) * BN + col) = v1;
    }
}

// ---------------- SpMM aggregation: warp per node, float4 per lane, 4-edge unroll ----------------
__global__ __launch_bounds__(128) void agg_kernel(
    const float4* __restrict__ support4, const int* __restrict__ rowptr,
    const int* __restrict__ ecol, const float* __restrict__ eval,
    const float4* __restrict__ bias4, float4* __restrict__ out4, int M)
{
    const int node = blockIdx.x * 4 + (threadIdx.x >> 5);
    const int lane = threadIdx.x & 31;
    if (node >= M) return;
    const int s = __ldg(&rowptr[node]);
    const int e = __ldg(&rowptr[node + 1]);
    float4 acc = make_float4(0.f, 0.f, 0.f, 0.f);
    int i = s;
    for (; i + 3 < e; i += 4) {
        int c0 = __ldg(&ecol[i]);
        int c1 = __ldg(&ecol[i + 1]);
        int c2 = __ldg(&ecol[i + 2]);
        int c3 = __ldg(&ecol[i + 3]);
        float v0 = __ldg(&eval[i]);
        float v1 = __ldg(&eval[i + 1]);
        float v2 = __ldg(&eval[i + 2]);
        float v3 = __ldg(&eval[i + 3]);
        float4 s0 = __ldg(&support4[(size_t)c0 * 32 + lane]);
        float4 s1 = __ldg(&support4[(size_t)c1 * 32 + lane]);
        float4 s2 = __ldg(&support4[(size_t)c2 * 32 + lane]);
        float4 s3 = __ldg(&support4[(size_t)c3 * 32 + lane]);
        acc.x += v0 * s0.x + v1 * s1.x + v2 * s2.x + v3 * s3.x;
        acc.y += v0 * s0.y + v1 * s1.y + v2 * s2.y + v3 * s3.y;
        acc.z += v0 * s0.z + v1 * s1.z + v2 * s2.z + v3 * s3.z;
        acc.w += v0 * s0.w + v1 * s1.w + v2 * s2.w + v3 * s3.w;
    }
    for (; i < e; i++) {
        int c0 = __ldg(&ecol[i]);
        float v0 = __ldg(&eval[i]);
        float4 s0 = __ldg(&support4[(size_t)c0 * 32 + lane]);
        acc.x += v0 * s0.x;
        acc.y += v0 * s0.y;
        acc.z += v0 * s0.z;
        acc.w += v0 * s0.w;
    }
    float4 b = __ldg(&bias4[lane]);
    float4 o;
    o.x = fmaxf(acc.x + b.x, 0.f);
    o.y = fmaxf(acc.y + b.y, 0.f);
    o.z = fmaxf(acc.z + b.z, 0.f);
    o.w = fmaxf(acc.w + b.w, 0.f);
    out4[(size_t)node * 32 + lane] = o;
}

// ---------------- final tiny layer ----------------
__global__ void mlp3_kernel(const float* __restrict__ h2, const float* __restrict__ W,
                            const float* __restrict__ b, float* __restrict__ out, int M)
{
    int n = blockIdx.x * blockDim.x + threadIdx.x;
    if (n >= M) return;
    float s0 = __ldg(&b[0]);
    float s1 = __ldg(&b[1]);
    const float* h = h2 + (size_t)n * 64;
    #pragma unroll
    for (int k4 = 0; k4 < 16; k4++) {
        float4 hv = *(const float4*)(h + 4 * k4);
        float4 w0, w1;
        w0.x = __ldg(&W[(4 * k4 + 0) * 2 + 0]); w1.x = __ldg(&W[(4 * k4 + 0) * 2 + 1]);
        w0.y = __ldg(&W[(4 * k4 + 1) * 2 + 0]); w1.y = __ldg(&W[(4 * k4 + 1) * 2 + 1]);
        w0.z = __ldg(&W[(4 * k4 + 2) * 2 + 0]); w1.z = __ldg(&W[(4 * k4 + 2) * 2 + 1]);
        w0.w = __ldg(&W[(4 * k4 + 3) * 2 + 0]); w1.w = __ldg(&W[(4 * k4 + 3) * 2 + 1]);
        s0 += hv.x * w0.x + hv.y * w0.y + hv.z * w0.z + hv.w * w0.w;
        s1 += hv.x * w1.x + hv.y * w1.y + hv.z * w1.z + hv.w * w1.w;
    }
    out[2 * n + 0] = s0;
    out[2 * n + 1] = s1;
}

// ---------------- launch ----------------
static void* sym_addr(const void* symbol) {
    void* p = nullptr;
    cudaGetSymbolAddress(&p, symbol);
    return p;
}

extern "C" void kernel_launch(void* const* d_in, const int* in_sizes, int n_in,
                              void* d_out, int out_size) {
    const int*   adj_row = (const int*)d_in[0];
    const int*   adj_col = (const int*)d_in[1];
    const float* adj_val = (const float*)d_in[2];
    const float* xin     = (const float*)d_in[3];
    const float* W1 = (const float*)d_in[5];
    const float* b1 = (const float*)d_in[6];
    const float* W2 = (const float*)d_in[7];
    const float* b2 = (const float*)d_in[8];
    const float* W3 = (const float*)d_in[9];
    const float* b3 = (const float*)d_in[10];
    const float* fcW1 = (const float*)d_in[11];
    const float* fcb1 = (const float*)d_in[12];
    const float* fcW2 = (const float*)d_in[13];
    const float* fcb2 = (const float*)d_in[14];
    const float* fcW3 = (const float*)d_in[15];
    const float* fcb3 = (const float*)d_in[16];

    const int E = in_sizes[0];
    const int M = in_sizes[4];

    int*   cnt     = (int*)sym_addr(g_cnt);
    int*   rowptr  = (int*)sym_addr(g_rowptr);
    int*   woff    = (int*)sym_addr(g_woff);
    int*   ecol    = (int*)sym_addr(g_ecol);
    float* eval    = (float*)sym_addr(g_eval);
    float* support = (float*)sym_addr(g_support);
    float* gg1     = (float*)sym_addr(g_g1);
    float* gg2     = (float*)sym_addr(g_g2);
    float* gg3     = (float*)sym_addr(g_g3);
    float* h1      = (float*)sym_addr(g_h1);
    float* h2      = (float*)sym_addr(g_h2);
    __nv_bfloat16* w1hi = (__nv_bfloat16*)sym_addr(g_w1hi);
    __nv_bfloat16* w1lo = (__nv_bfloat16*)sym_addr(g_w1lo);
    __nv_bfloat16* w2hi = (__nv_bfloat16*)sym_addr(g_w2hi);
    __nv_bfloat16* w2lo = (__nv_bfloat16*)sym_addr(g_w2lo);
    __nv_bfloat16* w3hi = (__nv_bfloat16*)sym_addr(g_w3hi);
    __nv_bfloat16* w3lo = (__nv_bfloat16*)sym_addr(g_w3lo);
    __nv_bfloat16* f1hi = (__nv_bfloat16*)sym_addr(g_f1hi);
    __nv_bfloat16* f1lo = (__nv_bfloat16*)sym_addr(g_f1lo);
    __nv_bfloat16* f2hi = (__nv_bfloat16*)sym_addr(g_f2hi);
    __nv_bfloat16* f2lo = (__nv_bfloat16*)sym_addr(g_f2lo);
    float* out     = (float*)d_out;

    constexpr int A_BYTES = 128 * 272;                       // 34816
    const int SMEM128 = 2 * A_BYTES + 2 * 128 * 272;         // 139264
    const int SMEM64  = 2 * A_BYTES + 2 * 64 * 272;          // 104448
    cudaFuncSetAttribute(gemm_mma<128, 1, false, false>, cudaFuncAttributeMaxDynamicSharedMemorySize, SMEM128);
    cudaFuncSetAttribute(gemm_mma<128, 1, false, true>,  cudaFuncAttributeMaxDynamicSharedMemorySize, SMEM128);
    cudaFuncSetAttribute(gemm_mma<128, 1, true, true>,   cudaFuncAttributeMaxDynamicSharedMemorySize, SMEM128);
    cudaFuncSetAttribute(gemm_mma<64, 1, true, false>,   cudaFuncAttributeMaxDynamicSharedMemorySize, SMEM64);

    // lazy one-time creation of side stream + events (host resources only)
    static cudaStream_t s_side = nullptr;
    static cudaEvent_t ev_root = nullptr, ev_csr = nullptr;
    static cudaEvent_t ev_a1 = nullptr, ev_a2 = nullptr, ev_a3 = nullptr, ev_fc1 = nullptr;
    if (s_side == nullptr) {
        cudaStreamCreateWithFlags(&s_side, cudaStreamNonBlocking);
        cudaEventCreateWithFlags(&ev_root, cudaEventDisableTiming);
        cudaEventCreateWithFlags(&ev_csr, cudaEventDisableTiming);
        cudaEventCreateWithFlags(&ev_a1, cudaEventDisableTiming);
        cudaEventCreateWithFlags(&ev_a2, cudaEventDisableTiming);
        cudaEventCreateWithFlags(&ev_a3, cudaEventDisableTiming);
        cudaEventCreateWithFlags(&ev_fc1, cudaEventDisableTiming);
    }

    const int gb = (M + 127) / 128;
    const int ab = (M + 3) / 4;

    // ---- fork: CSR build on side stream ----
    cudaEventRecord(ev_root, 0);
    cudaStreamWaitEvent(s_side, ev_root, 0);
    zero_cnt_kernel<<<(M + 255) / 256, 256, 0, s_side>>>(cnt, M);
    hist_kernel<<<(E + 255) / 256, 256, 0, s_side>>>(adj_row, cnt, E);
    scan_kernel<<<1, 1024, 0, s_side>>>(cnt, rowptr, woff, M);
    scatter_kernel<<<(E + 255) / 256, 256, 0, s_side>>>(adj_row, adj_col, adj_val, woff, ecol, eval, E);
    cudaEventRecord(ev_csr, s_side);

    // ---- main: fused weight split, then GCN chain ----
    wsplit_all_kernel<<<(106496 + 255) / 256, 256>>>(W1, W2, W3, fcW1, fcW2,
        w1hi, w1lo, w2hi, w2lo, w3hi, w3lo, f1hi, f1lo, f2hi, f2lo);

    gemm_mma<128, 1, false, false><<<gb, 256, SMEM128>>>(xin, nullptr, nullptr, w1hi, w1lo, nullptr, support, M, 128);

    cudaStreamWaitEvent(0, ev_csr, 0);
    agg_kernel<<<ab, 128>>>((const float4*)support, rowptr, ecol, eval, (const float4*)b1, (float4*)gg1, M);
    cudaEventRecord(ev_a1, 0);

    // side: fc1 partial 1 = g1 @ F1[0:128]  (overlaps gemm2/agg2)
    cudaStreamWaitEvent(s_side, ev_a1, 0);
    gemm_mma<128, 1, false, false><<<gb, 256, SMEM128, s_side>>>(gg1, nullptr, nullptr, f1hi, f1lo, nullptr, h1, M, 384);

    gemm_mma<128, 1, false, false><<<gb, 256, SMEM128>>>(gg1, nullptr, nullptr, w2hi, w2lo, nullptr, support, M, 128);
    agg_kernel<<<ab, 128>>>((const float4*)support, rowptr, ecol, eval, (const float4*)b2, (float4*)gg2, M);
    cudaEventRecord(ev_a2, 0);

    // side: fc1 partial 2 += g2 @ F1[128:256]
    cudaStreamWaitEvent(s_side, ev_a2, 0);
    gemm_mma<128, 1, false, true><<<gb, 256, SMEM128, s_side>>>(gg2, nullptr, nullptr, f1hi + 128, f1lo + 128, nullptr, h1, M, 384);

    gemm_mma<128, 1, false, false><<<gb, 256, SMEM128>>>(gg2, nullptr, nullptr, w3hi, w3lo, nullptr, support, M, 128);
    agg_kernel<<<ab, 128>>>((const float4*)support, rowptr, ecol, eval, (const float4*)b3, (float4*)gg3, M);
    cudaEventRecord(ev_a3, 0);

    // side: fc1 partial 3 += g3 @ F1[256:384], + bias + relu
    cudaStreamWaitEvent(s_side, ev_a3, 0);
    gemm_mma<128, 1, true, true><<<gb, 256, SMEM128, s_side>>>(gg3, nullptr, nullptr, f1hi + 256, f1lo + 256, fcb1, h1, M, 384);
    cudaEventRecord(ev_fc1, s_side);

    // main: tail
    cudaStreamWaitEvent(0, ev_fc1, 0);
    gemm_mma<64, 1, true, false><<<gb, 256, SMEM64>>>(h1, nullptr, nullptr, f2hi, f2lo, fcb2, h2, M, 128);
    mlp3_kernel<<<(M + 255) / 256, 256>>>(h2, fcW3, fcb3, out, M);
}

// round 13
// speedup vs baseline: 2.0813x; 1.0545x over previous
#include <cuda_runtime.h>
#include <cuda_bf16.h>
#include <cstdint>

// Problem constants
#define NN 50000
#define NE 800000

// ---------------- device scratch (static, no allocation) ----------------
__device__ int   g_cnt[NN];
__device__ int   g_rowptr[NN + 1];
__device__ int   g_woff[NN];
__device__ int   g_ecol[NE];
__device__ float g_eval[NE];
__device__ float g_support[(size_t)NN * 128];
__device__ float g_g1[(size_t)NN * 128];
__device__ float g_g2[(size_t)NN * 128];
__device__ float g_g3[(size_t)NN * 128];
__device__ float g_h1[(size_t)NN * 128];   // holds fc1 partials p1+p2 only
// per-layer transposed/split weights
__device__ __nv_bfloat16 g_w1hi[128 * 128], g_w1lo[128 * 128];
__device__ __nv_bfloat16 g_w2hi[128 * 128], g_w2lo[128 * 128];
__device__ __nv_bfloat16 g_w3hi[128 * 128], g_w3lo[128 * 128];
__device__ __nv_bfloat16 g_f1hi[128 * 384], g_f1lo[128 * 384];
__device__ __nv_bfloat16 g_f2hi[64 * 128],  g_f2lo[64 * 128];

// ---------------- helpers ----------------
__device__ __forceinline__ uint32_t smem_u32(const void* p) {
    uint32_t a;
    asm("{ .reg .u64 t; cvta.to.shared.u64 t, %1; cvt.u32.u64 %0, t; }" : "=r"(a) : "l"(p));
    return a;
}

#define LDSM4(r, addr) \
    asm volatile("ldmatrix.sync.aligned.m8n8.x4.shared.b16 {%0,%1,%2,%3}, [%4];" \
        : "=r"((r)[0]), "=r"((r)[1]), "=r"((r)[2]), "=r"((r)[3]) : "r"(addr))

#define MMA16816(d, a, b0, b1) \
    asm volatile("mma.sync.aligned.m16n8k16.row.col.f32.bf16.bf16.f32 " \
        "{%0,%1,%2,%3}, {%4,%5,%6,%7}, {%8,%9}, {%0,%1,%2,%3};" \
        : "+f"((d)[0]), "+f"((d)[1]), "+f"((d)[2]), "+f"((d)[3]) \
        : "r"((a)[0]), "r"((a)[1]), "r"((a)[2]), "r"((a)[3]), "r"(b0), "r"(b1))

// pack 8 fp32 -> uint4 of bf16 hi, uint4 of bf16 lo
__device__ __forceinline__ void split8(const float4& v0, const float4& v1,
                                       uint4& hi, uint4& lo) {
    __nv_bfloat162 h0 = __floats2bfloat162_rn(v0.x, v0.y);
    __nv_bfloat162 h1 = __floats2bfloat162_rn(v0.z, v0.w);
    __nv_bfloat162 h2 = __floats2bfloat162_rn(v1.x, v1.y);
    __nv_bfloat162 h3 = __floats2bfloat162_rn(v1.z, v1.w);
    __nv_bfloat162 l0 = __floats2bfloat162_rn(v0.x - __bfloat162float(h0.x), v0.y - __bfloat162float(h0.y));
    __nv_bfloat162 l1 = __floats2bfloat162_rn(v0.z - __bfloat162float(h1.x), v0.w - __bfloat162float(h1.y));
    __nv_bfloat162 l2 = __floats2bfloat162_rn(v1.x - __bfloat162float(h2.x), v1.y - __bfloat162float(h2.y));
    __nv_bfloat162 l3 = __floats2bfloat162_rn(v1.z - __bfloat162float(h3.x), v1.w - __bfloat162float(h3.y));
    hi.x = *(uint32_t*)&h0; hi.y = *(uint32_t*)&h1; hi.z = *(uint32_t*)&h2; hi.w = *(uint32_t*)&h3;
    lo.x = *(uint32_t*)&l0; lo.y = *(uint32_t*)&l1; lo.z = *(uint32_t*)&l2; lo.w = *(uint32_t*)&l3;
}

// ---------------- CSR build ----------------
__global__ void zero_cnt_kernel(int* __restrict__ cnt, int n) {
    int i = blockIdx.x * blockDim.x + threadIdx.x;
    if (i < n) cnt[i] = 0;
}

__global__ void hist_kernel(const int* __restrict__ row, int* __restrict__ cnt, int e) {
    int i = blockIdx.x * blockDim.x + threadIdx.x;
    if (i < e) atomicAdd(&cnt[row[i]], 1);
}

__global__ void scan_kernel(const int* __restrict__ cnt, int* __restrict__ rowptr,
                            int* __restrict__ woff, int n) {
    __shared__ int warp_sums[32];
    __shared__ int s_carry;
    int tid = threadIdx.x, lane = tid & 31, wid = tid >> 5;
    if (tid == 0) s_carry = 0;
    __syncthreads();
    for (int base = 0; base < n; base += 1024) {
        int carry = s_carry;
        int idx = base + tid;
        int x = (idx < n) ? cnt[idx] : 0;
        int v = x;
        #pragma unroll
        for (int off = 1; off < 32; off <<= 1) {
            int y = __shfl_up_sync(0xffffffffu, v, off);
            if (lane >= off) v += y;
        }
        if (lane == 31) warp_sums[wid] = v;
        __syncthreads();
        if (wid == 0) {
            int w = warp_sums[lane];
            #pragma unroll
            for (int off = 1; off < 32; off <<= 1) {
                int y = __shfl_up_sync(0xffffffffu, w, off);
                if (lane >= off) w += y;
            }
            warp_sums[lane] = w;
        }
        __syncthreads();
        int woffs = (wid > 0) ? warp_sums[wid - 1] : 0;
        int incl = v + woffs;
        if (idx < n) {
            int e = carry + incl - x;
            rowptr[idx] = e;
            woff[idx] = e;
        }
        __syncthreads();
        if (tid == 1023) s_carry = carry + incl;
        __syncthreads();
    }
    if (threadIdx.x == 0) rowptr[n] = s_carry;
}

__global__ void scatter_kernel(const int* __restrict__ row, const int* __restrict__ col,
                               const float* __restrict__ vals, int* __restrict__ woff,
                               int* __restrict__ ecol, float* __restrict__ eval, int e) {
    int i = blockIdx.x * blockDim.x + threadIdx.x;
    if (i < e) {
        int r = row[i];
        int p = atomicAdd(&woff[r], 1);
        ecol[p] = col[i];
        eval[p] = vals[i];
    }
}

// ---------------- fused weight transpose + bf16 split for all 5 matrices ----------------
__device__ __forceinline__ void wsplit_one(const float* __restrict__ W,
                                           __nv_bfloat16* __restrict__ hiT,
                                           __nv_bfloat16* __restrict__ loT,
                                           int j, int K, int N) {
    int k = j / N, n = j % N;
    float v = W[j];
    __nv_bfloat16 h = __float2bfloat16(v);
    float r = v - __bfloat162float(h);
    hiT[n * K + k] = h;
    loT[n * K + k] = __float2bfloat16(r);
}

__global__ void wsplit_all_kernel(
    const float* __restrict__ W1, const float* __restrict__ W2, const float* __restrict__ W3,
    const float* __restrict__ F1, const float* __restrict__ F2,
    __nv_bfloat16* __restrict__ w1hi, __nv_bfloat16* __restrict__ w1lo,
    __nv_bfloat16* __restrict__ w2hi, __nv_bfloat16* __restrict__ w2lo,
    __nv_bfloat16* __restrict__ w3hi, __nv_bfloat16* __restrict__ w3lo,
    __nv_bfloat16* __restrict__ f1hi, __nv_bfloat16* __restrict__ f1lo,
    __nv_bfloat16* __restrict__ f2hi, __nv_bfloat16* __restrict__ f2lo)
{
    int i = blockIdx.x * blockDim.x + threadIdx.x;
    if (i < 16384)       wsplit_one(W1, w1hi, w1lo, i, 128, 128);
    else if (i < 32768)  wsplit_one(W2, w2hi, w2lo, i - 16384, 128, 128);
    else if (i < 49152)  wsplit_one(W3, w3hi, w3lo, i - 32768, 128, 128);
    else if (i < 98304)  wsplit_one(F1, f1hi, f1lo, i - 49152, 384, 128);
    else if (i < 106496) wsplit_one(F2, f2hi, f2lo, i - 98304, 128, 64);
}

// ---- shared GEMM building blocks (BM=128, 256 threads, 8 warps x 16 rows) ----
#define LDAB 272
#define A_BYTES (128 * LDAB)

// stage fp32 X tile (128x128) -> bf16 hi/lo smem, padded rows; 8 iters, STS.128
__device__ __forceinline__ void stage_A(const float* __restrict__ xs, int m0, int M,
                                        char* pAhi, char* pAlo, int tid) {
    #pragma unroll
    for (int i = 0; i < 8; i++) {
        int f = tid + 256 * i;
        int row = f >> 4;
        int col = (f & 15) * 8;
        float4 v0 = make_float4(0.f, 0.f, 0.f, 0.f);
        float4 v1 = v0;
        int gm = m0 + row;
        if (gm < M) {
            v0 = *(const float4*)(xs + (size_t)gm * 128 + col);
            v1 = *(const float4*)(xs + (size_t)gm * 128 + col + 4);
        }
        uint4 hi, lo;
        split8(v0, v1, hi, lo);
        int off = LDAB * row + 2 * col;
        *(uint4*)(pAhi + off) = hi;
        *(uint4*)(pAlo + off) = lo;
    }
}

// stage pre-split B tile (BN x 128 hi/lo) from WT [N][wt_stride]
template <int BN>
__device__ __forceinline__ void stage_B(const __nv_bfloat16* __restrict__ WThi,
                                        const __nv_bfloat16* __restrict__ WTlo,
                                        int wt_stride, int kof,
                                        char* pBhi, char* pBlo, int tid) {
    #pragma unroll
    for (int i = 0; i < BN / 16; i++) {
        int f = tid + 256 * i;
        int row = f >> 4;
        int col = (f & 15) * 8;
        uint4 vh = *(const uint4*)(WThi + (size_t)row * wt_stride + kof + col);
        uint4 vl = *(const uint4*)(WTlo + (size_t)row * wt_stride + kof + col);
        int off = LDAB * row + 2 * col;
        *(uint4*)(pBhi + off) = vh;
        *(uint4*)(pBlo + off) = vl;
    }
}

// K=128 split-MMA mainloop: acc[NT][4] += A(128x128) @ B(BNx128)^T
template <int BN>
__device__ __forceinline__ void mma_loop(uint32_t a_hi_base, uint32_t a_lo_base,
                                         uint32_t b_hi_base, uint32_t b_lo_base,
                                         int b_bytes, float (*acc)[4]) {
    #pragma unroll
    for (int ks = 0; ks < 8; ks++) {
        uint32_t ah[4], al[4];
        LDSM4(ah, a_hi_base + 32 * ks);
        LDSM4(al, a_lo_base + 32 * ks);
        #pragma unroll
        for (int np = 0; np < BN / 16; np++) {
            uint32_t bh[4], bl[4];
            LDSM4(bh, b_hi_base + 16 * LDAB * np + 32 * ks);
            LDSM4(bl, b_lo_base + 16 * LDAB * np + 32 * ks);
            MMA16816(acc[2 * np],     ah, bh[0], bh[1]);
            MMA16816(acc[2 * np],     ah, bl[0], bl[1]);
            MMA16816(acc[2 * np],     al, bh[0], bh[1]);
            MMA16816(acc[2 * np + 1], ah, bh[2], bh[3]);
            MMA16816(acc[2 * np + 1], ah, bl[2], bl[3]);
            MMA16816(acc[2 * np + 1], al, bh[2], bh[3]);
        }
    }
}

// ---------------- standalone HMMA GEMM (BN=128, K=128) ----------------
template <bool ACCUM>
__global__ __launch_bounds__(256, 1)
void gemm_mma(const float* __restrict__ x0,
              const __nv_bfloat16* __restrict__ WThi, const __nv_bfloat16* __restrict__ WTlo,
              float* __restrict__ out, int M, int wt_stride)
{
    extern __shared__ char smem[];
    char* pAhi = smem;
    char* pAlo = smem + A_BYTES;
    char* pBhi = smem + 2 * A_BYTES;
    char* pBlo = smem + 3 * A_BYTES;

    const int tid = threadIdx.x, wid = tid >> 5, lane = tid & 31;
    const int m0 = blockIdx.x * 128;

    float acc[16][4];
    #pragma unroll
    for (int t = 0; t < 16; t++)
        #pragma unroll
        for (int j = 0; j < 4; j++) acc[t][j] = 0.f;

    const uint32_t sb = smem_u32(smem);
    const int mat = lane >> 3, r8 = lane & 7;
    const uint32_t a_hi_base = sb + LDAB * (wid * 16 + (mat & 1) * 8 + r8) + 16 * (mat >> 1);
    const uint32_t a_lo_base = a_hi_base + A_BYTES;
    const uint32_t b_hi_base = sb + 2 * A_BYTES + LDAB * ((mat >> 1) * 8 + r8) + 16 * (mat & 1);
    const uint32_t b_lo_base = b_hi_base + A_BYTES;

    stage_A(x0, m0, M, pAhi, pAlo, tid);
    stage_B<128>(WThi, WTlo, wt_stride, 0, pBhi, pBlo, tid);
    __syncthreads();
    mma_loop<128>(a_hi_base, a_lo_base, b_hi_base, b_lo_base, A_BYTES, acc);

    const int row0 = m0 + wid * 16 + (lane >> 2);
    const int coff = (lane & 3) * 2;
    #pragma unroll
    for (int t = 0; t < 16; t++) {
        int col = 8 * t + coff;
        float2 v0 = make_float2(acc[t][0], acc[t][1]);
        float2 v1 = make_float2(acc[t][2], acc[t][3]);
        if (ACCUM) {
            if (row0 < M) {
                float2 p = *(const float2*)(out + (size_t)row0 * 128 + col);
                v0.x += p.x; v0.y += p.y;
            }
            if (row0 + 8 < M) {
                float2 p = *(const float2*)(out + (size_t)(row0 + 8) * 128 + col);
                v1.x += p.x; v1.y += p.y;
            }
        }
        if (row0 < M)     *(float2*)(out + (size_t)row0 * 128 + col) = v0;
        if (row0 + 8 < M) *(float2*)(out + (size_t)(row0 + 8) * 128 + col) = v1;
    }
}

// ---------------- fused tail: h1 = relu(p12 + g3@F1c + b1), h2 = relu(h1@F2 + b2),
//                  logits = h2 @ W3 + b3 ----------------
__global__ __launch_bounds__(256, 1)
void tail_kernel(const float* __restrict__ g3,
                 const __nv_bfloat16* __restrict__ f1hi, const __nv_bfloat16* __restrict__ f1lo,
                 const float* __restrict__ p12, const float* __restrict__ fcb1,
                 const __nv_bfloat16* __restrict__ f2hi, const __nv_bfloat16* __restrict__ f2lo,
                 const float* __restrict__ fcb2,
                 const float* __restrict__ W3, const float* __restrict__ b3,
                 float* __restrict__ out, int M)
{
    extern __shared__ char smem[];
    char* pAhi = smem;
    char* pAlo = smem + A_BYTES;
    char* pBhi = smem + 2 * A_BYTES;
    char* pBlo = smem + 3 * A_BYTES;

    const int tid = threadIdx.x, wid = tid >> 5, lane = tid & 31;
    const int m0 = blockIdx.x * 128;

    const uint32_t sb = smem_u32(smem);
    const int mat = lane >> 3, r8 = lane & 7;
    const uint32_t a_hi_base = sb + LDAB * (wid * 16 + (mat & 1) * 8 + r8) + 16 * (mat >> 1);
    const uint32_t a_lo_base = a_hi_base + A_BYTES;
    const uint32_t b_hi_base = sb + 2 * A_BYTES + LDAB * ((mat >> 1) * 8 + r8) + 16 * (mat & 1);
    const uint32_t b_lo_base = b_hi_base + A_BYTES;

    // ---- stage 1: acc = g3 @ F1c ----
    float acc[16][4];
    #pragma unroll
    for (int t = 0; t < 16; t++)
        #pragma unroll
        for (int j = 0; j < 4; j++) acc[t][j] = 0.f;

    stage_A(g3, m0, M, pAhi, pAlo, tid);
    stage_B<128>(f1hi, f1lo, 384, 0, pBhi, pBlo, tid);
    __syncthreads();
    mma_loop<128>(a_hi_base, a_lo_base, b_hi_base, b_lo_base, A_BYTES, acc);

    // all warps done reading smem before restaging
    __syncthreads();

    // ---- epilogue 1: h1 = relu(acc + p12 + fcb1) -> smem bf16 hi/lo (A slot) ----
    const int rl0 = wid * 16 + (lane >> 2);   // local row
    const int coff = (lane & 3) * 2;
    #pragma unroll
    for (int t = 0; t < 16; t++) {
        int col = 8 * t + coff;
        float2 p0 = make_float2(0.f, 0.f), p1 = make_float2(0.f, 0.f);
        if (m0 + rl0 < M)     p0 = *(const float2*)(p12 + (size_t)(m0 + rl0) * 128 + col);
        if (m0 + rl0 + 8 < M) p1 = *(const float2*)(p12 + (size_t)(m0 + rl0 + 8) * 128 + col);
        float bb0 = __ldg(&fcb1[col]), bb1 = __ldg(&fcb1[col + 1]);
        float v00 = fmaxf(acc[t][0] + p0.x + bb0, 0.f);
        float v01 = fmaxf(acc[t][1] + p0.y + bb1, 0.f);
        float v10 = fmaxf(acc[t][2] + p1.x + bb0, 0.f);
        float v11 = fmaxf(acc[t][3] + p1.y + bb1, 0.f);
        __nv_bfloat162 h0 = __floats2bfloat162_rn(v00, v01);
        __nv_bfloat162 l0 = __floats2bfloat162_rn(v00 - __bfloat162float(h0.x), v01 - __bfloat162float(h0.y));
        __nv_bfloat162 h1v = __floats2bfloat162_rn(v10, v11);
        __nv_bfloat162 l1v = __floats2bfloat162_rn(v10 - __bfloat162float(h1v.x), v11 - __bfloat162float(h1v.y));
        int off0 = LDAB * rl0 + 2 * col;
        int off1 = LDAB * (rl0 + 8) + 2 * col;
        *(__nv_bfloat162*)(pAhi + off0) = h0;
        *(__nv_bfloat162*)(pAlo + off0) = l0;
        *(__nv_bfloat162*)(pAhi + off1) = h1v;
        *(__nv_bfloat162*)(pAlo + off1) = l1v;
    }
    // ---- stage F2 into B slot (64 rows) ----
    stage_B<64>(f2hi, f2lo, 128, 0, pBhi, pBlo, tid);
    __syncthreads();

    // ---- stage 2: acc2 = h1 @ F2 (BN=64) ----
    float acc2[8][4];
    #pragma unroll
    for (int t = 0; t < 8; t++)
        #pragma unroll
        for (int j = 0; j < 4; j++) acc2[t][j] = 0.f;
    mma_loop<64>(a_hi_base, a_lo_base, b_hi_base, b_lo_base, A_BYTES, acc2);

    __syncthreads();

    // ---- epilogue 2: h2 = relu(acc2 + fcb2) -> smem fp32, row stride 68 ----
    float* h2s = (float*)pAhi;   // 128 * 68 * 4 = 34816 bytes = A slot
    #pragma unroll
    for (int t = 0; t < 8; t++) {
        int col = 8 * t + coff;
        float bb0 = __ldg(&fcb2[col]), bb1 = __ldg(&fcb2[col + 1]);
        float2 v0 = make_float2(fmaxf(acc2[t][0] + bb0, 0.f), fmaxf(acc2[t][1] + bb1, 0.f));
        float2 v1 = make_float2(fmaxf(acc2[t][2] + bb0, 0.f), fmaxf(acc2[t][3] + bb1, 0.f));
        *(float2*)(h2s + (size_t)rl0 * 68 + col) = v0;
        *(float2*)(h2s + (size_t)(rl0 + 8) * 68 + col) = v1;
    }
    __syncthreads();

    // ---- in-kernel mlp3: logits = h2 @ W3 + b3 ----
    if (tid < 128) {
        int gm = m0 + tid;
        if (gm < M) {
            const float* h = h2s + (size_t)tid * 68;
            float s0 = __ldg(&b3[0]);
            float s1 = __ldg(&b3[1]);
            #pragma unroll
            for (int k4 = 0; k4 < 16; k4++) {
                float4 hv = *(const float4*)(h + 4 * k4);
                float4 w0, w1;
                w0.x = __ldg(&W3[(4 * k4 + 0) * 2 + 0]); w1.x = __ldg(&W3[(4 * k4 + 0) * 2 + 1]);
                w0.y = __ldg(&W3[(4 * k4 + 1) * 2 + 0]); w1.y = __ldg(&W3[(4 * k4 + 1) * 2 + 1]);
                w0.z = __ldg(&W3[(4 * k4 + 2) * 2 + 0]); w1.z = __ldg(&W3[(4 * k4 + 2) * 2 + 1]);
                w0.w = __ldg(&W3[(4 * k4 + 3) * 2 + 0]); w1.w = __ldg(&W3[(4 * k4 + 3) * 2 + 1]);
                s0 += hv.x * w0.x + hv.y * w0.y + hv.z * w0.z + hv.w * w0.w;
                s1 += hv.x * w1.x + hv.y * w1.y + hv.z * w1.z + hv.w * w1.w;
            }
            out[2 * gm + 0] = s0;
            out[2 * gm + 1] = s1;
        }
    }
}

// ---------------- SpMM aggregation: warp per node, float4 per lane, 4-edge unroll ----------------
__global__ __launch_bounds__(128) void agg_kernel(
    const float4* __restrict__ support4, const int* __restrict__ rowptr,
    const int* __restrict__ ecol, const float* __restrict__ eval,
    const float4* __restrict__ bias4, float4* __restrict__ out4, int M)
{
    const int node = blockIdx.x * 4 + (threadIdx.x >> 5);
    const int lane = threadIdx.x & 31;
    if (node >= M) return;
    const int s = __ldg(&rowptr[node]);
    const int e = __ldg(&rowptr[node + 1]);
    float4 acc = make_float4(0.f, 0.f, 0.f, 0.f);
    int i = s;
    for (; i + 3 < e; i += 4) {
        int c0 = __ldg(&ecol[i]);
        int c1 = __ldg(&ecol[i + 1]);
        int c2 = __ldg(&ecol[i + 2]);
        int c3 = __ldg(&ecol[i + 3]);
        float v0 = __ldg(&eval[i]);
        float v1 = __ldg(&eval[i + 1]);
        float v2 = __ldg(&eval[i + 2]);
        float v3 = __ldg(&eval[i + 3]);
        float4 s0 = __ldg(&support4[(size_t)c0 * 32 + lane]);
        float4 s1 = __ldg(&support4[(size_t)c1 * 32 + lane]);
        float4 s2 = __ldg(&support4[(size_t)c2 * 32 + lane]);
        float4 s3 = __ldg(&support4[(size_t)c3 * 32 + lane]);
        acc.x += v0 * s0.x + v1 * s1.x + v2 * s2.x + v3 * s3.x;
        acc.y += v0 * s0.y + v1 * s1.y + v2 * s2.y + v3 * s3.y;
        acc.z += v0 * s0.z + v1 * s1.z + v2 * s2.z + v3 * s3.z;
        acc.w += v0 * s0.w + v1 * s1.w + v2 * s2.w + v3 * s3.w;
    }
    for (; i < e; i++) {
        int c0 = __ldg(&ecol[i]);
        float v0 = __ldg(&eval[i]);
        float4 s0 = __ldg(&support4[(size_t)c0 * 32 + lane]);
        acc.x += v0 * s0.x;
        acc.y += v0 * s0.y;
        acc.z += v0 * s0.z;
        acc.w += v0 * s0.w;
    }
    float4 b = __ldg(&bias4[lane]);
    float4 o;
    o.x = fmaxf(acc.x + b.x, 0.f);
    o.y = fmaxf(acc.y + b.y, 0.f);
    o.z = fmaxf(acc.z + b.z, 0.f);
    o.w = fmaxf(acc.w + b.w, 0.f);
    out4[(size_t)node * 32 + lane] = o;
}

// ---------------- launch ----------------
static void* sym_addr(const void* symbol) {
    void* p = nullptr;
    cudaGetSymbolAddress(&p, symbol);
    return p;
}

extern "C" void kernel_launch(void* const* d_in, const int* in_sizes, int n_in,
                              void* d_out, int out_size) {
    const int*   adj_row = (const int*)d_in[0];
    const int*   adj_col = (const int*)d_in[1];
    const float* adj_val = (const float*)d_in[2];
    const float* xin     = (const float*)d_in[3];
    const float* W1 = (const float*)d_in[5];
    const float* b1 = (const float*)d_in[6];
    const float* W2 = (const float*)d_in[7];
    const float* b2 = (const float*)d_in[8];
    const float* W3 = (const float*)d_in[9];
    const float* b3 = (const float*)d_in[10];
    const float* fcW1 = (const float*)d_in[11];
    const float* fcb1 = (const float*)d_in[12];
    const float* fcW2 = (const float*)d_in[13];
    const float* fcb2 = (const float*)d_in[14];
    const float* fcW3 = (const float*)d_in[15];
    const float* fcb3 = (const float*)d_in[16];

    const int E = in_sizes[0];
    const int M = in_sizes[4];

    int*   cnt     = (int*)sym_addr(g_cnt);
    int*   rowptr  = (int*)sym_addr(g_rowptr);
    int*   woff    = (int*)sym_addr(g_woff);
    int*   ecol    = (int*)sym_addr(g_ecol);
    float* eval    = (float*)sym_addr(g_eval);
    float* support = (float*)sym_addr(g_support);
    float* gg1     = (float*)sym_addr(g_g1);
    float* gg2     = (float*)sym_addr(g_g2);
    float* gg3     = (float*)sym_addr(g_g3);
    float* h1      = (float*)sym_addr(g_h1);
    __nv_bfloat16* w1hi = (__nv_bfloat16*)sym_addr(g_w1hi);
    __nv_bfloat16* w1lo = (__nv_bfloat16*)sym_addr(g_w1lo);
    __nv_bfloat16* w2hi = (__nv_bfloat16*)sym_addr(g_w2hi);
    __nv_bfloat16* w2lo = (__nv_bfloat16*)sym_addr(g_w2lo);
    __nv_bfloat16* w3hi = (__nv_bfloat16*)sym_addr(g_w3hi);
    __nv_bfloat16* w3lo = (__nv_bfloat16*)sym_addr(g_w3lo);
    __nv_bfloat16* f1hi = (__nv_bfloat16*)sym_addr(g_f1hi);
    __nv_bfloat16* f1lo = (__nv_bfloat16*)sym_addr(g_f1lo);
    __nv_bfloat16* f2hi = (__nv_bfloat16*)sym_addr(g_f2hi);
    __nv_bfloat16* f2lo = (__nv_bfloat16*)sym_addr(g_f2lo);
    float* out     = (float*)d_out;

    const int SMEM = 4 * A_BYTES;  // 139264
    cudaFuncSetAttribute(gemm_mma<false>, cudaFuncAttributeMaxDynamicSharedMemorySize, SMEM);
    cudaFuncSetAttribute(gemm_mma<true>,  cudaFuncAttributeMaxDynamicSharedMemorySize, SMEM);
    cudaFuncSetAttribute(tail_kernel,     cudaFuncAttributeMaxDynamicSharedMemorySize, SMEM);

    // lazy one-time creation of side stream + events (host resources only)
    static cudaStream_t s_side = nullptr;
    static cudaEvent_t ev_root = nullptr, ev_csr = nullptr;
    static cudaEvent_t ev_a1 = nullptr, ev_a2 = nullptr, ev_p12 = nullptr;
    if (s_side == nullptr) {
        cudaStreamCreateWithFlags(&s_side, cudaStreamNonBlocking);
        cudaEventCreateWithFlags(&ev_root, cudaEventDisableTiming);
        cudaEventCreateWithFlags(&ev_csr, cudaEventDisableTiming);
        cudaEventCreateWithFlags(&ev_a1, cudaEventDisableTiming);
        cudaEventCreateWithFlags(&ev_a2, cudaEventDisableTiming);
        cudaEventCreateWithFlags(&ev_p12, cudaEventDisableTiming);
    }

    const int gb = (M + 127) / 128;
    const int ab = (M + 3) / 4;

    // ---- fork: CSR build on side stream ----
    cudaEventRecord(ev_root, 0);
    cudaStreamWaitEvent(s_side, ev_root, 0);
    zero_cnt_kernel<<<(M + 255) / 256, 256, 0, s_side>>>(cnt, M);
    hist_kernel<<<(E + 255) / 256, 256, 0, s_side>>>(adj_row, cnt, E);
    scan_kernel<<<1, 1024, 0, s_side>>>(cnt, rowptr, woff, M);
    scatter_kernel<<<(E + 255) / 256, 256, 0, s_side>>>(adj_row, adj_col, adj_val, woff, ecol, eval, E);
    cudaEventRecord(ev_csr, s_side);

    // ---- main: fused weight split, then GCN chain ----
    wsplit_all_kernel<<<(106496 + 255) / 256, 256>>>(W1, W2, W3, fcW1, fcW2,
        w1hi, w1lo, w2hi, w2lo, w3hi, w3lo, f1hi, f1lo, f2hi, f2lo);

    gemm_mma<false><<<gb, 256, SMEM>>>(xin, w1hi, w1lo, support, M, 128);

    cudaStreamWaitEvent(0, ev_csr, 0);
    agg_kernel<<<ab, 128>>>((const float4*)support, rowptr, ecol, eval, (const float4*)b1, (float4*)gg1, M);
    cudaEventRecord(ev_a1, 0);

    // side: fc1 partial 1 = g1 @ F1[0:128]
    cudaStreamWaitEvent(s_side, ev_a1, 0);
    gemm_mma<false><<<gb, 256, SMEM, s_side>>>(gg1, f1hi, f1lo, h1, M, 384);

    gemm_mma<false><<<gb, 256, SMEM>>>(gg1, w2hi, w2lo, support, M, 128);
    agg_kernel<<<ab, 128>>>((const float4*)support, rowptr, ecol, eval, (const float4*)b2, (float4*)gg2, M);
    cudaEventRecord(ev_a2, 0);

    // side: fc1 partial 2 += g2 @ F1[128:256]
    cudaStreamWaitEvent(s_side, ev_a2, 0);
    gemm_mma<true><<<gb, 256, SMEM, s_side>>>(gg2, f1hi + 128, f1lo + 128, h1, M, 384);
    cudaEventRecord(ev_p12, s_side);

    gemm_mma<false><<<gb, 256, SMEM>>>(gg2, w3hi, w3lo, support, M, 128);
    agg_kernel<<<ab, 128>>>((const float4*)support, rowptr, ecol, eval, (const float4*)b3, (float4*)gg3, M);

    // ---- fused tail: p3 + fc2 + mlp3 in one kernel ----
    cudaStreamWaitEvent(0, ev_p12, 0);
    tail_kernel<<<gb, 256, SMEM>>>(gg3, f1hi + 256, f1lo + 256, h1, fcb1,
                                   f2hi, f2lo, fcb2, fcW3, fcb3, out, M);
}

// round 16
// speedup vs baseline: 2.2373x; 1.0750x over previous
#include <cuda_runtime.h>
#include <cuda_bf16.h>
#include <cstdint>

// Problem constants
#define NN 50000
#define NE 800000

// ---------------- device scratch (static, no allocation) ----------------
__device__ int   g_cnt[NN];
__device__ int   g_rowptr[NN + 1];
__device__ int   g_woff[NN];
__device__ int   g_bsum[64];
__device__ int   g_bscan[64];
__device__ int2  g_edge[NE];           // packed (col, val-as-int)
__device__ float g_support[(size_t)NN * 128];
__device__ float g_g1[(size_t)NN * 128];
__device__ float g_g2[(size_t)NN * 128];
__device__ float g_g3[(size_t)NN * 128];
__device__ float g_h1[(size_t)NN * 128];   // fc1 partials p1+p2
// per-layer transposed/split weights
__device__ __nv_bfloat16 g_w1hi[128 * 128], g_w1lo[128 * 128];
__device__ __nv_bfloat16 g_w2hi[128 * 128], g_w2lo[128 * 128];
__device__ __nv_bfloat16 g_w3hi[128 * 128], g_w3lo[128 * 128];
__device__ __nv_bfloat16 g_f1hi[128 * 384], g_f1lo[128 * 384];
__device__ __nv_bfloat16 g_f2hi[64 * 128],  g_f2lo[64 * 128];

// ---------------- helpers ----------------
__device__ __forceinline__ uint32_t smem_u32(const void* p) {
    uint32_t a;
    asm("{ .reg .u64 t; cvta.to.shared.u64 t, %1; cvt.u32.u64 %0, t; }" : "=r"(a) : "l"(p));
    return a;
}

#define LDSM4(r, addr) \
    asm volatile("ldmatrix.sync.aligned.m8n8.x4.shared.b16 {%0,%1,%2,%3}, [%4];" \
        : "=r"((r)[0]), "=r"((r)[1]), "=r"((r)[2]), "=r"((r)[3]) : "r"(addr))

#define MMA16816(d, a, b0, b1) \
    asm volatile("mma.sync.aligned.m16n8k16.row.col.f32.bf16.bf16.f32 " \
        "{%0,%1,%2,%3}, {%4,%5,%6,%7}, {%8,%9}, {%0,%1,%2,%3};" \
        : "+f"((d)[0]), "+f"((d)[1]), "+f"((d)[2]), "+f"((d)[3]) \
        : "r"((a)[0]), "r"((a)[1]), "r"((a)[2]), "r"((a)[3]), "r"(b0), "r"(b1))

// pack 8 fp32 -> uint4 of bf16 hi, uint4 of bf16 lo
__device__ __forceinline__ void split8(const float4& v0, const float4& v1,
                                       uint4& hi, uint4& lo) {
    __nv_bfloat162 h0 = __floats2bfloat162_rn(v0.x, v0.y);
    __nv_bfloat162 h1 = __floats2bfloat162_rn(v0.z, v0.w);
    __nv_bfloat162 h2 = __floats2bfloat162_rn(v1.x, v1.y);
    __nv_bfloat162 h3 = __floats2bfloat162_rn(v1.z, v1.w);
    __nv_bfloat162 l0 = __floats2bfloat162_rn(v0.x - __bfloat162float(h0.x), v0.y - __bfloat162float(h0.y));
    __nv_bfloat162 l1 = __floats2bfloat162_rn(v0.z - __bfloat162float(h1.x), v0.w - __bfloat162float(h1.y));
    __nv_bfloat162 l2 = __floats2bfloat162_rn(v1.x - __bfloat162float(h2.x), v1.y - __bfloat162float(h2.y));
    __nv_bfloat162 l3 = __floats2bfloat162_rn(v1.z - __bfloat162float(h3.x), v1.w - __bfloat162float(h3.y));
    hi.x = *(uint32_t*)&h0; hi.y = *(uint32_t*)&h1; hi.z = *(uint32_t*)&h2; hi.w = *(uint32_t*)&h3;
    lo.x = *(uint32_t*)&l0; lo.y = *(uint32_t*)&l1; lo.z = *(uint32_t*)&l2; lo.w = *(uint32_t*)&l3;
}

// ---------------- CSR build ----------------
__global__ void zero_cnt_kernel(int* __restrict__ cnt, int n) {
    int i = blockIdx.x * blockDim.x + threadIdx.x;
    if (i < n) cnt[i] = 0;
}

// vectorized histogram: 4 edges per thread via int4
__global__ void hist_kernel(const int* __restrict__ row, int* __restrict__ cnt, int e) {
    int i = blockIdx.x * blockDim.x + threadIdx.x;
    int e4 = e >> 2;
    if (i < e4) {
        int4 r = __ldg(&((const int4*)row)[i]);
        atomicAdd(&cnt[r.x], 1);
        atomicAdd(&cnt[r.y], 1);
        atomicAdd(&cnt[r.z], 1);
        atomicAdd(&cnt[r.w], 1);
    }
    if (i < (e & 3)) atomicAdd(&cnt[row[4 * e4 + i]], 1);
}

// scan phase A: per-1024-block exclusive scan of cnt into rowptr; block totals to bsum
__global__ __launch_bounds__(1024) void scanA_kernel(const int* __restrict__ cnt,
                                                     int* __restrict__ rowptr,
                                                     int* __restrict__ bsum, int n) {
    __shared__ int warp_sums[32];
    int tid = threadIdx.x, lane = tid & 31, wid = tid >> 5;
    int idx = blockIdx.x * 1024 + tid;
    int x = (idx < n) ? cnt[idx] : 0;
    int v = x;
    #pragma unroll
    for (int off = 1; off < 32; off <<= 1) {
        int y = __shfl_up_sync(0xffffffffu, v, off);
        if (lane >= off) v += y;
    }
    if (lane == 31) warp_sums[wid] = v;
    __syncthreads();
    if (wid == 0) {
        int w = warp_sums[lane];
        #pragma unroll
        for (int off = 1; off < 32; off <<= 1) {
            int y = __shfl_up_sync(0xffffffffu, w, off);
            if (lane >= off) w += y;
        }
        warp_sums[lane] = w;
    }
    __syncthreads();
    int woffs = (wid > 0) ? warp_sums[wid - 1] : 0;
    if (idx < n) rowptr[idx] = woffs + v - x;
    if (tid == 0) bsum[blockIdx.x] = warp_sums[31];
}

// scan phase B: one warp scans nb block sums (exclusive) -> bscan; total -> rowptr[n]
__global__ void scanB_kernel(const int* __restrict__ bsum, int* __restrict__ bscan,
                             int nb, int* __restrict__ rowptr_n) {
    int lane = threadIdx.x & 31;
    int carry = 0;
    for (int base = 0; base < nb; base += 32) {
        int x = (base + lane < nb) ? bsum[base + lane] : 0;
        int v = x;
        #pragma unroll
        for (int off = 1; off < 32; off <<= 1) {
            int y = __shfl_up_sync(0xffffffffu, v, off);
            if (lane >= off) v += y;
        }
        if (base + lane < nb) bscan[base + lane] = carry + v - x;
        carry += __shfl_sync(0xffffffffu, v, 31);
    }
    if (lane == 0) rowptr_n[0] = carry;
}

// scan phase C: add block offsets, mirror into woff
__global__ __launch_bounds__(1024) void scanC_kernel(int* __restrict__ rowptr,
                                                     int* __restrict__ woff,
                                                     const int* __restrict__ bscan, int n) {
    int idx = blockIdx.x * 1024 + threadIdx.x;
    if (idx < n) {
        int r = rowptr[idx] + bscan[blockIdx.x];
        rowptr[idx] = r;
        woff[idx] = r;
    }
}

__global__ void scatter_kernel(const int* __restrict__ row, const int* __restrict__ col,
                               const float* __restrict__ vals, int* __restrict__ woff,
                               int2* __restrict__ edge, int e) {
    int i = blockIdx.x * blockDim.x + threadIdx.x;
    if (i < e) {
        int r = row[i];
        int p = atomicAdd(&woff[r], 1);
        edge[p] = make_int2(col[i], __float_as_int(vals[i]));
    }
}

// ---------------- fused weight transpose + bf16 split for all 5 matrices ----------------
__device__ __forceinline__ void wsplit_one(const float* __restrict__ W,
                                           __nv_bfloat16* __restrict__ hiT,
                                           __nv_bfloat16* __restrict__ loT,
                                           int j, int K, int N) {
    int k = j / N, n = j % N;
    float v = W[j];
    __nv_bfloat16 h = __float2bfloat16(v);
    float r = v - __bfloat162float(h);
    hiT[n * K + k] = h;
    loT[n * K + k] = __float2bfloat16(r);
}

__global__ void wsplit_all_kernel(
    const float* __restrict__ W1, const float* __restrict__ W2, const float* __restrict__ W3,
    const float* __restrict__ F1, const float* __restrict__ F2,
    __nv_bfloat16* __restrict__ w1hi, __nv_bfloat16* __restrict__ w1lo,
    __nv_bfloat16* __restrict__ w2hi, __nv_bfloat16* __restrict__ w2lo,
    __nv_bfloat16* __restrict__ w3hi, __nv_bfloat16* __restrict__ w3lo,
    __nv_bfloat16* __restrict__ f1hi, __nv_bfloat16* __restrict__ f1lo,
    __nv_bfloat16* __restrict__ f2hi, __nv_bfloat16* __restrict__ f2lo)
{
    int i = blockIdx.x * blockDim.x + threadIdx.x;
    if (i < 16384)       wsplit_one(W1, w1hi, w1lo, i, 128, 128);
    else if (i < 32768)  wsplit_one(W2, w2hi, w2lo, i - 16384, 128, 128);
    else if (i < 49152)  wsplit_one(W3, w3hi, w3lo, i - 32768, 128, 128);
    else if (i < 98304)  wsplit_one(F1, f1hi, f1lo, i - 49152, 384, 128);
    else if (i < 106496) wsplit_one(F2, f2hi, f2lo, i - 98304, 128, 64);
}

// ---- shared GEMM building blocks (BM=128, 256 threads, 8 warps x 16 rows) ----
#define LDAB 272
#define A_BYTES (128 * LDAB)

__device__ __forceinline__ void stage_A(const float* __restrict__ xs, int m0, int M,
                                        char* pAhi, char* pAlo, int tid) {
    #pragma unroll
    for (int i = 0; i < 8; i++) {
        int f = tid + 256 * i;
        int row = f >> 4;
        int col = (f & 15) * 8;
        float4 v0 = make_float4(0.f, 0.f, 0.f, 0.f);
        float4 v1 = v0;
        int gm = m0 + row;
        if (gm < M) {
            v0 = *(const float4*)(xs + (size_t)gm * 128 + col);
            v1 = *(const float4*)(xs + (size_t)gm * 128 + col + 4);
        }
        uint4 hi, lo;
        split8(v0, v1, hi, lo);
        int off = LDAB * row + 2 * col;
        *(uint4*)(pAhi + off) = hi;
        *(uint4*)(pAlo + off) = lo;
    }
}

template <int BN>
__device__ __forceinline__ void stage_B(const __nv_bfloat16* __restrict__ WThi,
                                        const __nv_bfloat16* __restrict__ WTlo,
                                        int wt_stride, int kof,
                                        char* pBhi, char* pBlo, int tid) {
    #pragma unroll
    for (int i = 0; i < BN / 16; i++) {
        int f = tid + 256 * i;
        int row = f >> 4;
        int col = (f & 15) * 8;
        uint4 vh = *(const uint4*)(WThi + (size_t)row * wt_stride + kof + col);
        uint4 vl = *(const uint4*)(WTlo + (size_t)row * wt_stride + kof + col);
        int off = LDAB * row + 2 * col;
        *(uint4*)(pBhi + off) = vh;
        *(uint4*)(pBlo + off) = vl;
    }
}

template <int BN>
__device__ __forceinline__ void mma_loop(uint32_t a_hi_base, uint32_t a_lo_base,
                                         uint32_t b_hi_base, uint32_t b_lo_base,
                                         int b_bytes, float (*acc)[4]) {
    #pragma unroll
    for (int ks = 0; ks < 8; ks++) {
        uint32_t ah[4], al[4];
        LDSM4(ah, a_hi_base + 32 * ks);
        LDSM4(al, a_lo_base + 32 * ks);
        #pragma unroll
        for (int np = 0; np < BN / 16; np++) {
            uint32_t bh[4], bl[4];
            LDSM4(bh, b_hi_base + 16 * LDAB * np + 32 * ks);
            LDSM4(bl, b_lo_base + 16 * LDAB * np + 32 * ks);
            MMA16816(acc[2 * np],     ah, bh[0], bh[1]);
            MMA16816(acc[2 * np],     ah, bl[0], bl[1]);
            MMA16816(acc[2 * np],     al, bh[0], bh[1]);
            MMA16816(acc[2 * np + 1], ah, bh[2], bh[3]);
            MMA16816(acc[2 * np + 1], ah, bl[2], bl[3]);
            MMA16816(acc[2 * np + 1], al, bh[2], bh[3]);
        }
    }
}

// ---------------- standalone HMMA GEMM (BN=128, K=128) ----------------
template <bool ACCUM>
__global__ __launch_bounds__(256, 1)
void gemm_mma(const float* __restrict__ x0,
              const __nv_bfloat16* __restrict__ WThi, const __nv_bfloat16* __restrict__ WTlo,
              float* __restrict__ out, int M, int wt_stride)
{
    extern __shared__ char smem[];
    char* pAhi = smem;
    char* pAlo = smem + A_BYTES;
    char* pBhi = smem + 2 * A_BYTES;
    char* pBlo = smem + 3 * A_BYTES;

    const int tid = threadIdx.x, wid = tid >> 5, lane = tid & 31;
    const int m0 = blockIdx.x * 128;

    float acc[16][4];
    #pragma unroll
    for (int t = 0; t < 16; t++)
        #pragma unroll
        for (int j = 0; j < 4; j++) acc[t][j] = 0.f;

    const uint32_t sb = smem_u32(smem);
    const int mat = lane >> 3, r8 = lane & 7;
    const uint32_t a_hi_base = sb + LDAB * (wid * 16 + (mat & 1) * 8 + r8) + 16 * (mat >> 1);
    const uint32_t a_lo_base = a_hi_base + A_BYTES;
    const uint32_t b_hi_base = sb + 2 * A_BYTES + LDAB * ((mat >> 1) * 8 + r8) + 16 * (mat & 1);
    const uint32_t b_lo_base = b_hi_base + A_BYTES;

    stage_A(x0, m0, M, pAhi, pAlo, tid);
    stage_B<128>(WThi, WTlo, wt_stride, 0, pBhi, pBlo, tid);
    __syncthreads();
    mma_loop<128>(a_hi_base, a_lo_base, b_hi_base, b_lo_base, A_BYTES, acc);

    const int row0 = m0 + wid * 16 + (lane >> 2);
    const int coff = (lane & 3) * 2;
    #pragma unroll
    for (int t = 0; t < 16; t++) {
        int col = 8 * t + coff;
        float2 v0 = make_float2(acc[t][0], acc[t][1]);
        float2 v1 = make_float2(acc[t][2], acc[t][3]);
        if (ACCUM) {
            if (row0 < M) {
                float2 p = *(const float2*)(out + (size_t)row0 * 128 + col);
                v0.x += p.x; v0.y += p.y;
            }
            if (row0 + 8 < M) {
                float2 p = *(const float2*)(out + (size_t)(row0 + 8) * 128 + col);
                v1.x += p.x; v1.y += p.y;
            }
        }
        if (row0 < M)     *(float2*)(out + (size_t)row0 * 128 + col) = v0;
        if (row0 + 8 < M) *(float2*)(out + (size_t)(row0 + 8) * 128 + col) = v1;
    }
}

// ---------------- fused tail: h1 = relu(p12 + g3@F1c + b1), h2 = relu(h1@F2 + b2),
//                  logits = h2 @ W3 + b3 ----------------
__global__ __launch_bounds__(256, 1)
void tail_kernel(const float* __restrict__ g3,
                 const __nv_bfloat16* __restrict__ f1hi, const __nv_bfloat16* __restrict__ f1lo,
                 const float* __restrict__ p12, const float* __restrict__ fcb1,
                 const __nv_bfloat16* __restrict__ f2hi, const __nv_bfloat16* __restrict__ f2lo,
                 const float* __restrict__ fcb2,
                 const float* __restrict__ W3, const float* __restrict__ b3,
                 float* __restrict__ out, int M)
{
    extern __shared__ char smem[];
    char* pAhi = smem;
    char* pAlo = smem + A_BYTES;
    char* pBhi = smem + 2 * A_BYTES;
    char* pBlo = smem + 3 * A_BYTES;

    const int tid = threadIdx.x, wid = tid >> 5, lane = tid & 31;
    const int m0 = blockIdx.x * 128;

    const uint32_t sb = smem_u32(smem);
    const int mat = lane >> 3, r8 = lane & 7;
    const uint32_t a_hi_base = sb + LDAB * (wid * 16 + (mat & 1) * 8 + r8) + 16 * (mat >> 1);
    const uint32_t a_lo_base = a_hi_base + A_BYTES;
    const uint32_t b_hi_base = sb + 2 * A_BYTES + LDAB * ((mat >> 1) * 8 + r8) + 16 * (mat & 1);
    const uint32_t b_lo_base = b_hi_base + A_BYTES;

    // ---- stage 1: acc = g3 @ F1c ----
    float acc[16][4];
    #pragma unroll
    for (int t = 0; t < 16; t++)
        #pragma unroll
        for (int j = 0; j < 4; j++) acc[t][j] = 0.f;

    stage_A(g3, m0, M, pAhi, pAlo, tid);
    stage_B<128>(f1hi, f1lo, 384, 0, pBhi, pBlo, tid);
    __syncthreads();
    mma_loop<128>(a_hi_base, a_lo_base, b_hi_base, b_lo_base, A_BYTES, acc);
    __syncthreads();

    // ---- epilogue 1: h1 = relu(acc + p12 + fcb1) -> smem bf16 hi/lo (A slot) ----
    const int rl0 = wid * 16 + (lane >> 2);
    const int coff = (lane & 3) * 2;
    #pragma unroll
    for (int t = 0; t < 16; t++) {
        int col = 8 * t + coff;
        float2 p0 = make_float2(0.f, 0.f), p1 = make_float2(0.f, 0.f);
        if (m0 + rl0 < M)     p0 = *(const float2*)(p12 + (size_t)(m0 + rl0) * 128 + col);
        if (m0 + rl0 + 8 < M) p1 = *(const float2*)(p12 + (size_t)(m0 + rl0 + 8) * 128 + col);
        float bb0 = __ldg(&fcb1[col]), bb1 = __ldg(&fcb1[col + 1]);
        float v00 = fmaxf(acc[t][0] + p0.x + bb0, 0.f);
        float v01 = fmaxf(acc[t][1] + p0.y + bb1, 0.f);
        float v10 = fmaxf(acc[t][2] + p1.x + bb0, 0.f);
        float v11 = fmaxf(acc[t][3] + p1.y + bb1, 0.f);
        __nv_bfloat162 h0 = __floats2bfloat162_rn(v00, v01);
        __nv_bfloat162 l0 = __floats2bfloat162_rn(v00 - __bfloat162float(h0.x), v01 - __bfloat162float(h0.y));
        __nv_bfloat162 h1v = __floats2bfloat162_rn(v10, v11);
        __nv_bfloat162 l1v = __floats2bfloat162_rn(v10 - __bfloat162float(h1v.x), v11 - __bfloat162float(h1v.y));
        int off0 = LDAB * rl0 + 2 * col;
        int off1 = LDAB * (rl0 + 8) + 2 * col;
        *(__nv_bfloat162*)(pAhi + off0) = h0;
        *(__nv_bfloat162*)(pAlo + off0) = l0;
        *(__nv_bfloat162*)(pAhi + off1) = h1v;
        *(__nv_bfloat162*)(pAlo + off1) = l1v;
    }
    stage_B<64>(f2hi, f2lo, 128, 0, pBhi, pBlo, tid);
    __syncthreads();

    // ---- stage 2: acc2 = h1 @ F2 (BN=64) ----
    float acc2[8][4];
    #pragma unroll
    for (int t = 0; t < 8; t++)
        #pragma unroll
        for (int j = 0; j < 4; j++) acc2[t][j] = 0.f;
    mma_loop<64>(a_hi_base, a_lo_base, b_hi_base, b_lo_base, A_BYTES, acc2);
    __syncthreads();

    // ---- epilogue 2: h2 = relu(acc2 + fcb2) -> smem fp32, row stride 68 ----
    float* h2s = (float*)pAhi;
    #pragma unroll
    for (int t = 0; t < 8; t++) {
        int col = 8 * t + coff;
        float bb0 = __ldg(&fcb2[col]), bb1 = __ldg(&fcb2[col + 1]);
        float2 v0 = make_float2(fmaxf(acc2[t][0] + bb0, 0.f), fmaxf(acc2[t][1] + bb1, 0.f));
        float2 v1 = make_float2(fmaxf(acc2[t][2] + bb0, 0.f), fmaxf(acc2[t][3] + bb1, 0.f));
        *(float2*)(h2s + (size_t)rl0 * 68 + col) = v0;
        *(float2*)(h2s + (size_t)(rl0 + 8) * 68 + col) = v1;
    }
    __syncthreads();

    // ---- in-kernel mlp3 ----
    if (tid < 128) {
        int gm = m0 + tid;
        if (gm < M) {
            const float* h = h2s + (size_t)tid * 68;
            float s0 = __ldg(&b3[0]);
            float s1 = __ldg(&b3[1]);
            #pragma unroll
            for (int k4 = 0; k4 < 16; k4++) {
                float4 hv = *(const float4*)(h + 4 * k4);
                float4 w0, w1;
                w0.x = __ldg(&W3[(4 * k4 + 0) * 2 + 0]); w1.x = __ldg(&W3[(4 * k4 + 0) * 2 + 1]);
                w0.y = __ldg(&W3[(4 * k4 + 1) * 2 + 0]); w1.y = __ldg(&W3[(4 * k4 + 1) * 2 + 1]);
                w0.z = __ldg(&W3[(4 * k4 + 2) * 2 + 0]); w1.z = __ldg(&W3[(4 * k4 + 2) * 2 + 1]);
                w0.w = __ldg(&W3[(4 * k4 + 3) * 2 + 0]); w1.w = __ldg(&W3[(4 * k4 + 3) * 2 + 1]);
                s0 += hv.x * w0.x + hv.y * w0.y + hv.z * w0.z + hv.w * w0.w;
                s1 += hv.x * w1.x + hv.y * w1.y + hv.z * w1.z + hv.w * w1.w;
            }
            out[2 * gm + 0] = s0;
            out[2 * gm + 1] = s1;
        }
    }
}

// ---------------- SpMM aggregation: warp per node, packed int2 edges ----------------
__global__ __launch_bounds__(256) void agg_kernel(
    const float4* __restrict__ support4, const int* __restrict__ rowptr,
    const int2* __restrict__ edge,
    const float4* __restrict__ bias4, float4* __restrict__ out4, int M)
{
    const int node = blockIdx.x * 8 + (threadIdx.x >> 5);
    const int lane = threadIdx.x & 31;
    if (node >= M) return;
    const int s = __ldg(&rowptr[node]);
    const int e = __ldg(&rowptr[node + 1]);
    float4 acc = make_float4(0.f, 0.f, 0.f, 0.f);
    int i = s;
    for (; i + 3 < e; i += 4) {
        int2 e0 = __ldg(&edge[i]);
        int2 e1 = __ldg(&edge[i + 1]);
        int2 e2 = __ldg(&edge[i + 2]);
        int2 e3 = __ldg(&edge[i + 3]);
        float4 s0 = __ldg(&support4[(size_t)e0.x * 32 + lane]);
        float4 s1 = __ldg(&support4[(size_t)e1.x * 32 + lane]);
        float4 s2 = __ldg(&support4[(size_t)e2.x * 32 + lane]);
        float4 s3 = __ldg(&support4[(size_t)e3.x * 32 + lane]);
        float v0 = __int_as_float(e0.y), v1 = __int_as_float(e1.y);
        float v2 = __int_as_float(e2.y), v3 = __int_as_float(e3.y);
        acc.x += v0 * s0.x + v1 * s1.x + v2 * s2.x + v3 * s3.x;
        acc.y += v0 * s0.y + v1 * s1.y + v2 * s2.y + v3 * s3.y;
        acc.z += v0 * s0.z + v1 * s1.z + v2 * s2.z + v3 * s3.z;
        acc.w += v0 * s0.w + v1 * s1.w + v2 * s2.w + v3 * s3.w;
    }
    for (; i < e; i++) {
        int2 e0 = __ldg(&edge[i]);
        float v0 = __int_as_float(e0.y);
        float4 s0 = __ldg(&support4[(size_t)e0.x * 32 + lane]);
        acc.x += v0 * s0.x;
        acc.y += v0 * s0.y;
        acc.z += v0 * s0.z;
        acc.w += v0 * s0.w;
    }
    float4 b = __ldg(&bias4[lane]);
    float4 o;
    o.x = fmaxf(acc.x + b.x, 0.f);
    o.y = fmaxf(acc.y + b.y, 0.f);
    o.z = fmaxf(acc.z + b.z, 0.f);
    o.w = fmaxf(acc.w + b.w, 0.f);
    out4[(size_t)node * 32 + lane] = o;
}

// ---------------- launch ----------------
static void* sym_addr(const void* symbol) {
    void* p = nullptr;
    cudaGetSymbolAddress(&p, symbol);
    return p;
}

extern "C" void kernel_launch(void* const* d_in, const int* in_sizes, int n_in,
                              void* d_out, int out_size) {
    const int*   adj_row = (const int*)d_in[0];
    const int*   adj_col = (const int*)d_in[1];
    const float* adj_val = (const float*)d_in[2];
    const float* xin     = (const float*)d_in[3];
    const float* W1 = (const float*)d_in[5];
    const float* b1 = (const float*)d_in[6];
    const float* W2 = (const float*)d_in[7];
    const float* b2 = (const float*)d_in[8];
    const float* W3 = (const float*)d_in[9];
    const float* b3 = (const float*)d_in[10];
    const float* fcW1 = (const float*)d_in[11];
    const float* fcb1 = (const float*)d_in[12];
    const float* fcW2 = (const float*)d_in[13];
    const float* fcb2 = (const float*)d_in[14];
    const float* fcW3 = (const float*)d_in[15];
    const float* fcb3 = (const float*)d_in[16];

    const int E = in_sizes[0];
    const int M = in_sizes[4];

    int*   cnt     = (int*)sym_addr(g_cnt);
    int*   rowptr  = (int*)sym_addr(g_rowptr);
    int*   woff    = (int*)sym_addr(g_woff);
    int*   bsum    = (int*)sym_addr(g_bsum);
    int*   bscan   = (int*)sym_addr(g_bscan);
    int2*  edge    = (int2*)sym_addr(g_edge);
    float* support = (float*)sym_addr(g_support);
    float* gg1     = (float*)sym_addr(g_g1);
    float* gg2     = (float*)sym_addr(g_g2);
    float* gg3     = (float*)sym_addr(g_g3);
    float* h1      = (float*)sym_addr(g_h1);
    __nv_bfloat16* w1hi = (__nv_bfloat16*)sym_addr(g_w1hi);
    __nv_bfloat16* w1lo = (__nv_bfloat16*)sym_addr(g_w1lo);
    __nv_bfloat16* w2hi = (__nv_bfloat16*)sym_addr(g_w2hi);
    __nv_bfloat16* w2lo = (__nv_bfloat16*)sym_addr(g_w2lo);
    __nv_bfloat16* w3hi = (__nv_bfloat16*)sym_addr(g_w3hi);
    __nv_bfloat16* w3lo = (__nv_bfloat16*)sym_addr(g_w3lo);
    __nv_bfloat16* f1hi = (__nv_bfloat16*)sym_addr(g_f1hi);
    __nv_bfloat16* f1lo = (__nv_bfloat16*)sym_addr(g_f1lo);
    __nv_bfloat16* f2hi = (__nv_bfloat16*)sym_addr(g_f2hi);
    __nv_bfloat16* f2lo = (__nv_bfloat16*)sym_addr(g_f2lo);
    float* out     = (float*)d_out;

    const int SMEM = 4 * A_BYTES;  // 139264
    cudaFuncSetAttribute(gemm_mma<false>, cudaFuncAttributeMaxDynamicSharedMemorySize, SMEM);
    cudaFuncSetAttribute(gemm_mma<true>,  cudaFuncAttributeMaxDynamicSharedMemorySize, SMEM);
    cudaFuncSetAttribute(tail_kernel,     cudaFuncAttributeMaxDynamicSharedMemorySize, SMEM);

    static cudaStream_t s_side = nullptr;
    static cudaEvent_t ev_root = nullptr, ev_csr = nullptr;
    static cudaEvent_t ev_a1 = nullptr, ev_a2 = nullptr, ev_p12 = nullptr;
    if (s_side == nullptr) {
        cudaStreamCreateWithFlags(&s_side, cudaStreamNonBlocking);
        cudaEventCreateWithFlags(&ev_root, cudaEventDisableTiming);
        cudaEventCreateWithFlags(&ev_csr, cudaEventDisableTiming);
        cudaEventCreateWithFlags(&ev_a1, cudaEventDisableTiming);
        cudaEventCreateWithFlags(&ev_a2, cudaEventDisableTiming);
        cudaEventCreateWithFlags(&ev_p12, cudaEventDisableTiming);
    }

    const int gb = (M + 127) / 128;
    const int ab = (M + 7) / 8;
    const int nb = (M + 1023) / 1024;

    // ---- fork: CSR build on side stream ----
    cudaEventRecord(ev_root, 0);
    cudaStreamWaitEvent(s_side, ev_root, 0);
    zero_cnt_kernel<<<(M + 255) / 256, 256, 0, s_side>>>(cnt, M);
    hist_kernel<<<(E / 4 + 255) / 256, 256, 0, s_side>>>(adj_row, cnt, E);
    scanA_kernel<<<nb, 1024, 0, s_side>>>(cnt, rowptr, bsum, M);
    scanB_kernel<<<1, 32, 0, s_side>>>(bsum, bscan, nb, rowptr + M);
    scanC_kernel<<<nb, 1024, 0, s_side>>>(rowptr, woff, bscan, M);
    scatter_kernel<<<(E + 255) / 256, 256, 0, s_side>>>(adj_row, adj_col, adj_val, woff, edge, E);
    cudaEventRecord(ev_csr, s_side);

    // ---- main: fused weight split, then GCN chain ----
    wsplit_all_kernel<<<(106496 + 255) / 256, 256>>>(W1, W2, W3, fcW1, fcW2,
        w1hi, w1lo, w2hi, w2lo, w3hi, w3lo, f1hi, f1lo, f2hi, f2lo);

    gemm_mma<false><<<gb, 256, SMEM>>>(xin, w1hi, w1lo, support, M, 128);

    cudaStreamWaitEvent(0, ev_csr, 0);
    agg_kernel<<<ab, 256>>>((const float4*)support, rowptr, edge, (const float4*)b1, (float4*)gg1, M);
    cudaEventRecord(ev_a1, 0);

    // side: fc1 partial 1 = g1 @ F1[0:128]
    cudaStreamWaitEvent(s_side, ev_a1, 0);
    gemm_mma<false><<<gb, 256, SMEM, s_side>>>(gg1, f1hi, f1lo, h1, M, 384);

    gemm_mma<false><<<gb, 256, SMEM>>>(gg1, w2hi, w2lo, support, M, 128);
    agg_kernel<<<ab, 256>>>((const float4*)support, rowptr, edge, (const float4*)b2, (float4*)gg2, M);
    cudaEventRecord(ev_a2, 0);

    // side: fc1 partial 2 += g2 @ F1[128:256]
    cudaStreamWaitEvent(s_side, ev_a2, 0);
    gemm_mma<true><<<gb, 256, SMEM, s_side>>>(gg2, f1hi + 128, f1lo + 128, h1, M, 384);
    cudaEventRecord(ev_p12, s_side);

    gemm_mma<false><<<gb, 256, SMEM>>>(gg2, w3hi, w3lo, support, M, 128);
    agg_kernel<<<ab, 256>>>((const float4*)support, rowptr, edge, (const float4*)b3, (float4*)gg3, M);

    // ---- fused tail: p3 + fc2 + mlp3 ----
    cudaStreamWaitEvent(0, ev_p12, 0);
    tail_kernel<<<gb, 256, SMEM>>>(gg3, f1hi + 256, f1lo + 256, h1, fcb1,
                                   f2hi, f2lo, fcb2, fcW3, fcb3, out, M);
}